// round 4
// baseline (speedup 1.0000x reference)
#include <cuda_runtime.h>
#include <cuda_bf16.h>
#include <math.h>
#include <stdint.h>

#define B_   2
#define S_   2048
#define H_   2048
#define NH_  16
#define NKV_ 4
#define DH_  128
#define I_   8192
#define M_   (B_ * S_)          // 4096 tokens
#define GROUPS_ (NH_ / NKV_)    // 4
#define EPS_ 1e-6f

#define QKV_N_ 3072             // 2048 q + 512 k + 512 v
#define GU_N_  16384            // 8192 gate + 8192 up

// ---------------- scratch (device globals; no runtime allocation) ----------------
__device__ float g_xnorm[(size_t)M_ * H_];
__device__ float g_qkv[(size_t)M_ * QKV_N_];
__device__ float g_attn[(size_t)M_ * H_];
__device__ float g_h1[(size_t)M_ * H_];
__device__ float g_x2[(size_t)M_ * H_];
__device__ float g_gu[(size_t)M_ * GU_N_];
__device__ float g_act[(size_t)M_ * I_];
// tf32-converted weights
__device__ float w_qkv[(size_t)H_ * QKV_N_];
__device__ float w_o[(size_t)H_ * H_];
__device__ float w_gu[(size_t)H_ * GU_N_];
__device__ float w_dn[(size_t)I_ * H_];

// ---------------- helpers ----------------
__device__ __forceinline__ float to_tf32(float x) {
    uint32_t r;
    asm("cvt.rna.tf32.f32 %0, %1;" : "=r"(r) : "f"(x));
    return __uint_as_float(r);
}

__device__ __forceinline__ uint32_t smem_u32(const void* p) {
    return (uint32_t)__cvta_generic_to_shared(p);
}

__device__ __forceinline__ void cp_async16(uint32_t dst, const void* src) {
    asm volatile("cp.async.cg.shared.global [%0], [%1], 16;\n" :: "r"(dst), "l"(src));
}
__device__ __forceinline__ void cp_commit() { asm volatile("cp.async.commit_group;\n"); }
__device__ __forceinline__ void cp_wait0()  { asm volatile("cp.async.wait_group 0;\n"); }

__device__ __forceinline__ void mma_tf32(float* d, const uint32_t* a, uint32_t b0, uint32_t b1) {
    asm volatile(
        "mma.sync.aligned.m16n8k8.row.col.f32.tf32.tf32.f32 "
        "{%0,%1,%2,%3}, {%4,%5,%6,%7}, {%8,%9}, {%0,%1,%2,%3};\n"
        : "+f"(d[0]), "+f"(d[1]), "+f"(d[2]), "+f"(d[3])
        : "r"(a[0]), "r"(a[1]), "r"(a[2]), "r"(a[3]), "r"(b0), "r"(b1));
}

// ---------------- weight convert (fp32 -> tf32) with column placement ----------------
// src: [rows][ncols4*4] row-major; dst row stride dstStride4 float4s, column offset colOff4.
__global__ void cvt2d_kernel(const float* __restrict__ src, float* __restrict__ dst,
                             int ncols4, int dstStride4, int colOff4, long total4) {
    long i = (long)blockIdx.x * blockDim.x + threadIdx.x;
    if (i >= total4) return;
    long r = i / ncols4;
    int c = (int)(i - r * ncols4);
    float4 v = ((const float4*)src)[i];
    v.x = to_tf32(v.x); v.y = to_tf32(v.y); v.z = to_tf32(v.z); v.w = to_tf32(v.w);
    ((float4*)dst)[r * (long)dstStride4 + colOff4 + c] = v;
}

// ---------------- RMSNorm over rows of length Hdim, output tf32 ----------------
__global__ void rmsnorm_kernel(const float* __restrict__ x, const float* __restrict__ w,
                               float* __restrict__ y, int Hdim) {
    int row = blockIdx.x;
    const float4* xr = (const float4*)(x + (size_t)row * Hdim);
    float4* yr = (float4*)(y + (size_t)row * Hdim);
    const float4* wv = (const float4*)w;
    int n4 = Hdim >> 2;

    float ss = 0.f;
    for (int i = threadIdx.x; i < n4; i += blockDim.x) {
        float4 v = xr[i];
        ss += v.x * v.x + v.y * v.y + v.z * v.z + v.w * v.w;
    }
    __shared__ float wsum[8];
    for (int o = 16; o > 0; o >>= 1) ss += __shfl_xor_sync(0xffffffffu, ss, o);
    int warp = threadIdx.x >> 5;
    if ((threadIdx.x & 31) == 0) wsum[warp] = ss;
    __syncthreads();
    __shared__ float s_inv;
    if (threadIdx.x == 0) {
        float t = 0.f;
        #pragma unroll
        for (int i = 0; i < 8; i++) t += wsum[i];
        s_inv = rsqrtf(t / (float)Hdim + EPS_);
    }
    __syncthreads();
    float inv = s_inv;
    for (int i = threadIdx.x; i < n4; i += blockDim.x) {
        float4 v = xr[i];
        float4 ww = wv[i];
        float4 o;
        o.x = to_tf32(v.x * inv * ww.x); o.y = to_tf32(v.y * inv * ww.y);
        o.z = to_tf32(v.z * inv * ww.z); o.w = to_tf32(v.w * inv * ww.w);
        yr[i] = o;
    }
}

// ---------------- per-(token,head) RMSNorm + RoPE, DH=128, 128 threads ----------------
__global__ void qknorm_rope_kernel(float* __restrict__ base, int rowStride,
                                   const float* __restrict__ w,
                                   const float* __restrict__ cosp, const float* __restrict__ sinp,
                                   int nheads) {
    int idx = blockIdx.x;
    int head = idx % nheads;
    int token = idx / nheads;
    float* p = base + (size_t)token * rowStride + head * DH_;
    int d = threadIdx.x;

    float v = p[d];
    float ss = v * v;
    for (int o = 16; o > 0; o >>= 1) ss += __shfl_xor_sync(0xffffffffu, ss, o);
    __shared__ float wsum[4];
    int warp = d >> 5;
    if ((d & 31) == 0) wsum[warp] = ss;
    __syncthreads();
    float tot = wsum[0] + wsum[1] + wsum[2] + wsum[3];
    float inv = rsqrtf(tot / (float)DH_ + EPS_);
    float vn = v * inv * w[d];

    __shared__ float sh[DH_];
    sh[d] = vn;
    __syncthreads();
    float other = (d < 64) ? -sh[d + 64] : sh[d - 64];
    float c = cosp[(size_t)token * DH_ + d];
    float s = sinp[(size_t)token * DH_ + d];
    p[d] = vn * c + other * s;
}

// ---------------- tf32 tensor-core GEMM ----------------
// C[M,N] = A[M,K] @ B[K,N] (+ Res). A,B already tf32-quantized fp32 bit patterns.
// 128x128x32 block tile, 4 warps (128 thr), warp tile 64x64, m16n8k8 tf32 mma,
// 2-stage cp.async pipeline. Requires M%128==0, N%128==0, K%32==0.
#define G_STAGE (128 * 36 + 32 * 136)   // floats per stage: As + Bs

__device__ __forceinline__ void gemm_issue(const float* __restrict__ Abase,
                                           const float* __restrict__ Bm, long N, long colBase,
                                           float* As, float* Bs, int tid, int k0) {
    uint32_t aDst = smem_u32(As + tid * 36);
    const float* aSrc = Abase + k0;
    #pragma unroll
    for (int i = 0; i < 8; i++)
        cp_async16(aDst + i * 16, aSrc + i * 4);
    #pragma unroll
    for (int p = 0; p < 8; p++) {
        int f = tid + p * 128;
        int kr = f >> 5, n4 = f & 31;
        cp_async16(smem_u32(Bs + kr * 136 + n4 * 4),
                   Bm + (long)(k0 + kr) * N + colBase + n4 * 4);
    }
}

__device__ __forceinline__ void gemm_compute(const float* As, const float* Bs,
                                             int wm, int wn, int gid, int tig,
                                             float (&acc)[4][8][4]) {
    #pragma unroll
    for (int kk = 0; kk < 32; kk += 8) {
        uint32_t a[4][4];
        #pragma unroll
        for (int mi = 0; mi < 4; mi++) {
            const float* ap = As + (wm + mi * 16 + gid) * 36;
            a[mi][0] = __float_as_uint(ap[kk + tig]);
            a[mi][1] = __float_as_uint(ap[8 * 36 + kk + tig]);
            a[mi][2] = __float_as_uint(ap[kk + tig + 4]);
            a[mi][3] = __float_as_uint(ap[8 * 36 + kk + tig + 4]);
        }
        #pragma unroll
        for (int ni = 0; ni < 8; ni++) {
            uint32_t b0 = __float_as_uint(Bs[(kk + tig) * 136 + wn + ni * 8 + gid]);
            uint32_t b1 = __float_as_uint(Bs[(kk + tig + 4) * 136 + wn + ni * 8 + gid]);
            #pragma unroll
            for (int mi = 0; mi < 4; mi++)
                mma_tf32(acc[mi][ni], a[mi], b0, b1);
        }
    }
}

__global__ __launch_bounds__(128) void gemm_tf32(const float* __restrict__ A,
                                                 const float* __restrict__ Bm,
                                                 const float* __restrict__ Res,
                                                 float* __restrict__ C,
                                                 int M, int N, int K) {
    extern __shared__ float sm[];
    int tid = threadIdx.x;
    int wid = tid >> 5, lane = tid & 31;
    int gid = lane >> 2, tig = lane & 3;
    int wm = (wid >> 1) * 64, wn = (wid & 1) * 64;
    long rowBase = (long)blockIdx.y * 128;
    long colBase = (long)blockIdx.x * 128;

    float acc[4][8][4] = {};

    const float* Abase = A + (rowBase + tid) * (long)K;
    float* As0 = sm;
    float* Bs0 = sm + 128 * 36;
    float* As1 = sm + G_STAGE;
    float* Bs1 = As1 + 128 * 36;

    int nIter = K / 32;
    gemm_issue(Abase, Bm, N, colBase, As0, Bs0, tid, 0);
    cp_commit();
    cp_wait0();
    __syncthreads();

    for (int it = 0; it < nIter; it++) {
        int cur = it & 1;
        if (it + 1 < nIter) {
            gemm_issue(Abase, Bm, N, colBase, cur ? As0 : As1, cur ? Bs0 : Bs1,
                       tid, (it + 1) * 32);
            cp_commit();
        }
        gemm_compute(cur ? As1 : As0, cur ? Bs1 : Bs0, wm, wn, gid, tig, acc);
        if (it + 1 < nIter) {
            cp_wait0();
            __syncthreads();
        }
    }

    // epilogue
    #pragma unroll
    for (int mi = 0; mi < 4; mi++) {
        #pragma unroll
        for (int ni = 0; ni < 8; ni++) {
            long r0 = rowBase + wm + mi * 16 + gid;
            long c = colBase + wn + ni * 8 + tig * 2;
            float2 v0 = make_float2(acc[mi][ni][0], acc[mi][ni][1]);
            float2 v1 = make_float2(acc[mi][ni][2], acc[mi][ni][3]);
            if (Res != nullptr) {
                float2 r0v = *(const float2*)(Res + r0 * N + c);
                float2 r1v = *(const float2*)(Res + (r0 + 8) * N + c);
                v0.x += r0v.x; v0.y += r0v.y;
                v1.x += r1v.x; v1.y += r1v.y;
            }
            *(float2*)(C + r0 * N + c) = v0;
            *(float2*)(C + (r0 + 8) * N + c) = v1;
        }
    }
}

// ---------------- Flash attention, fp32, reads from fused qkv buffer ----------------
#define ATTN_SMEM_FLOATS (2 * 64 * 129 + 64 * 128 + 64 * 65)
__global__ __launch_bounds__(256) void attn_kernel(const float* __restrict__ qkv,
                                                   float* __restrict__ o) {
    extern __shared__ float sm[];
    float* Qs = sm;                 // 64 x 129
    float* Ks = Qs + 64 * 129;      // 64 x 129
    float* Vs = Ks + 64 * 129;      // 64 x 128
    float* Ps = Vs + 64 * 128;      // 64 x 65

    int qb = blockIdx.x, h = blockIdx.y, b = blockIdx.z;
    int kvh = h / GROUPS_;
    int tid = threadIdx.x;
    int tx = tid & 15, ty = tid >> 4;

    const float scale = 0.08838834764831845f;  // 1/sqrt(128)

    for (int s = tid; s < 64 * 32; s += 256) {
        int r = s >> 5;
        int c4 = (s & 31) * 4;
        int srow = qb * 64 + r;
        float4 qv = *(const float4*)(qkv + (size_t)(b * S_ + srow) * QKV_N_ + h * DH_ + c4);
        Qs[r * 129 + c4 + 0] = qv.x * scale;
        Qs[r * 129 + c4 + 1] = qv.y * scale;
        Qs[r * 129 + c4 + 2] = qv.z * scale;
        Qs[r * 129 + c4 + 3] = qv.w * scale;
    }

    float m[4], l[4], acc[4][8];
    #pragma unroll
    for (int i = 0; i < 4; i++) {
        m[i] = -INFINITY; l[i] = 0.f;
        #pragma unroll
        for (int dd = 0; dd < 8; dd++) acc[i][dd] = 0.f;
    }

    for (int kt = 0; kt < S_ / 64; kt++) {
        __syncthreads();
        for (int s = tid; s < 64 * 32; s += 256) {
            int r = s >> 5;
            int c4 = (s & 31) * 4;
            int j = kt * 64 + r;
            size_t gbase = (size_t)(b * S_ + j) * QKV_N_ + kvh * DH_ + c4;
            float4 kv = *(const float4*)(qkv + 2048 + gbase);
            Ks[r * 129 + c4 + 0] = kv.x;
            Ks[r * 129 + c4 + 1] = kv.y;
            Ks[r * 129 + c4 + 2] = kv.z;
            Ks[r * 129 + c4 + 3] = kv.w;
            *(float4*)&Vs[r * 128 + c4] = *(const float4*)(qkv + 2560 + gbase);
        }
        __syncthreads();

        float sc[4][4];
        #pragma unroll
        for (int i = 0; i < 4; i++)
            #pragma unroll
            for (int j = 0; j < 4; j++) sc[i][j] = 0.f;
        for (int d = 0; d < DH_; d++) {
            float qr[4], kr[4];
            #pragma unroll
            for (int i = 0; i < 4; i++) qr[i] = Qs[(ty * 4 + i) * 129 + d];
            #pragma unroll
            for (int j = 0; j < 4; j++) kr[j] = Ks[(tx * 4 + j) * 129 + d];
            #pragma unroll
            for (int i = 0; i < 4; i++)
                #pragma unroll
                for (int j = 0; j < 4; j++) sc[i][j] = fmaf(qr[i], kr[j], sc[i][j]);
        }

        #pragma unroll
        for (int i = 0; i < 4; i++) {
            float tmax = sc[i][0];
            #pragma unroll
            for (int j = 1; j < 4; j++) tmax = fmaxf(tmax, sc[i][j]);
            #pragma unroll
            for (int off = 1; off < 16; off <<= 1)
                tmax = fmaxf(tmax, __shfl_xor_sync(0xffffffffu, tmax, off));
            float newm = fmaxf(m[i], tmax);
            float psum = 0.f;
            #pragma unroll
            for (int j = 0; j < 4; j++) {
                float p = __expf(sc[i][j] - newm);
                sc[i][j] = p;
                psum += p;
            }
            #pragma unroll
            for (int off = 1; off < 16; off <<= 1)
                psum += __shfl_xor_sync(0xffffffffu, psum, off);
            float alpha = __expf(m[i] - newm);
            l[i] = l[i] * alpha + psum;
            m[i] = newm;
            #pragma unroll
            for (int dd = 0; dd < 8; dd++) acc[i][dd] *= alpha;
            #pragma unroll
            for (int j = 0; j < 4; j++) Ps[(ty * 4 + i) * 65 + tx * 4 + j] = sc[i][j];
        }
        __syncthreads();

        for (int j = 0; j < 64; j++) {
            float vv[8];
            #pragma unroll
            for (int dd = 0; dd < 8; dd++) vv[dd] = Vs[j * 128 + tx * 8 + dd];
            #pragma unroll
            for (int i = 0; i < 4; i++) {
                float p = Ps[(ty * 4 + i) * 65 + j];
                #pragma unroll
                for (int dd = 0; dd < 8; dd++) acc[i][dd] = fmaf(p, vv[dd], acc[i][dd]);
            }
        }
    }

    #pragma unroll
    for (int i = 0; i < 4; i++) {
        int srow = qb * 64 + ty * 4 + i;
        float invl = 1.f / l[i];
        size_t base = (((size_t)(b * S_ + srow)) * NH_ + h) * DH_ + tx * 8;
        #pragma unroll
        for (int dd = 0; dd < 8; dd++) o[base + dd] = to_tf32(acc[i][dd] * invl);
    }
}

// ---------------- silu(gate) * up from fused gu buffer, tf32 output ----------------
__global__ void silu_mul_kernel(const float* __restrict__ gu, float* __restrict__ out, long total4) {
    long i = (long)blockIdx.x * blockDim.x + threadIdx.x;
    if (i >= total4) return;
    long mrow = i >> 11;             // / 2048 float4 per out row
    int c4 = (int)(i & 2047);
    const float4* gu4 = (const float4*)gu;
    float4 gv = gu4[mrow * 4096 + c4];
    float4 uv = gu4[mrow * 4096 + 2048 + c4];
    float4 o;
    o.x = to_tf32(gv.x / (1.f + __expf(-gv.x)) * uv.x);
    o.y = to_tf32(gv.y / (1.f + __expf(-gv.y)) * uv.y);
    o.z = to_tf32(gv.z / (1.f + __expf(-gv.z)) * uv.z);
    o.w = to_tf32(gv.w / (1.f + __expf(-gv.w)) * uv.w);
    ((float4*)out)[i] = o;
}

// ---------------- launch ----------------
static inline void launch_cvt(const float* src, float* dst, int ncols4, int stride4, int off4, long total4) {
    int blocks = (int)((total4 + 255) / 256);
    cvt2d_kernel<<<blocks, 256>>>(src, dst, ncols4, stride4, off4, total4);
}

extern "C" void kernel_launch(void* const* d_in, const int* in_sizes, int n_in,
                              void* d_out, int out_size) {
    const float* hidden = (const float*)d_in[0];
    const float* cosp   = (const float*)d_in[1];
    const float* sinp   = (const float*)d_in[2];
    const float* wq     = (const float*)d_in[3];
    const float* wk     = (const float*)d_in[4];
    const float* wv     = (const float*)d_in[5];
    const float* wo     = (const float*)d_in[6];
    const float* qnw    = (const float*)d_in[7];
    const float* knw    = (const float*)d_in[8];
    const float* anw    = (const float*)d_in[9];
    const float* mnw    = (const float*)d_in[10];
    const float* wgate  = (const float*)d_in[11];
    const float* wup    = (const float*)d_in[12];
    const float* wdown  = (const float*)d_in[13];
    float* out = (float*)d_out;

    float *xnorm, *qkv, *attn, *h1, *x2, *gu, *act;
    float *Wqkv, *Wo, *Wgu, *Wdn;
    cudaGetSymbolAddress((void**)&xnorm, g_xnorm);
    cudaGetSymbolAddress((void**)&qkv, g_qkv);
    cudaGetSymbolAddress((void**)&attn, g_attn);
    cudaGetSymbolAddress((void**)&h1, g_h1);
    cudaGetSymbolAddress((void**)&x2, g_x2);
    cudaGetSymbolAddress((void**)&gu, g_gu);
    cudaGetSymbolAddress((void**)&act, g_act);
    cudaGetSymbolAddress((void**)&Wqkv, w_qkv);
    cudaGetSymbolAddress((void**)&Wo, w_o);
    cudaGetSymbolAddress((void**)&Wgu, w_gu);
    cudaGetSymbolAddress((void**)&Wdn, w_dn);

    const int attn_smem = ATTN_SMEM_FLOATS * sizeof(float);
    cudaFuncSetAttribute(attn_kernel, cudaFuncAttributeMaxDynamicSharedMemorySize, attn_smem);
    const int gemm_smem = 2 * G_STAGE * sizeof(float);
    cudaFuncSetAttribute(gemm_tf32, cudaFuncAttributeMaxDynamicSharedMemorySize, gemm_smem);

    // 0) convert weights to tf32 (fused/concatenated layouts)
    launch_cvt(wq,    Wqkv, 512,  768,  0,    (long)H_ * 512);        // [2048 x 2048] -> cols 0..2047
    launch_cvt(wk,    Wqkv, 128,  768,  512,  (long)H_ * 128);        // -> cols 2048..2559
    launch_cvt(wv,    Wqkv, 128,  768,  640,  (long)H_ * 128);        // -> cols 2560..3071
    launch_cvt(wo,    Wo,   512,  512,  0,    (long)H_ * 512);
    launch_cvt(wgate, Wgu,  2048, 4096, 0,    (long)H_ * 2048);       // -> cols 0..8191
    launch_cvt(wup,   Wgu,  2048, 4096, 2048, (long)H_ * 2048);       // -> cols 8192..16383
    launch_cvt(wdown, Wdn,  512,  512,  0,    (long)I_ * 512);

    // 1) attn rmsnorm (tf32 out)
    rmsnorm_kernel<<<M_, 256>>>(hidden, anw, xnorm, H_);

    // 2) fused QKV projection
    gemm_tf32<<<dim3(QKV_N_ / 128, M_ / 128), 128, gemm_smem>>>(xnorm, Wqkv, nullptr, qkv, M_, QKV_N_, H_);

    // 3) q/k norm + rope (in place in qkv buffer)
    qknorm_rope_kernel<<<M_ * NH_, DH_>>>(qkv, QKV_N_, qnw, cosp, sinp, NH_);
    qknorm_rope_kernel<<<M_ * NKV_, DH_>>>(qkv + 2048, QKV_N_, knw, cosp, sinp, NKV_);

    // 4) attention (tf32 out)
    attn_kernel<<<dim3(S_ / 64, NH_, B_), 256, attn_smem>>>(qkv, attn);

    // 5) O projection + residual
    gemm_tf32<<<dim3(H_ / 128, M_ / 128), 128, gemm_smem>>>(attn, Wo, hidden, h1, M_, H_, H_);

    // 6) mlp rmsnorm (tf32 out)
    rmsnorm_kernel<<<M_, 256>>>(h1, mnw, x2, H_);

    // 7) fused gate+up projection
    gemm_tf32<<<dim3(GU_N_ / 128, M_ / 128), 128, gemm_smem>>>(x2, Wgu, nullptr, gu, M_, GU_N_, H_);

    // 8) silu * up (tf32 out)
    {
        long total4 = (long)M_ * I_ / 4;
        int blocks = (int)((total4 + 255) / 256);
        silu_mul_kernel<<<blocks, 256>>>(gu, act, total4);
    }

    // 9) down projection + residual -> output
    gemm_tf32<<<dim3(H_ / 128, M_ / 128), 128, gemm_smem>>>(act, Wdn, h1, out, M_, H_, I_);
}

// round 5
// speedup vs baseline: 2.3030x; 2.3030x over previous
#include <cuda_runtime.h>
#include <cuda_bf16.h>
#include <math.h>
#include <stdint.h>

#define B_   2
#define S_   2048
#define H_   2048
#define NH_  16
#define NKV_ 4
#define DH_  128
#define I_   8192
#define M_   (B_ * S_)          // 4096 tokens
#define GROUPS_ (NH_ / NKV_)    // 4
#define EPS_ 1e-6f

#define QKV_N_ 3072             // 2048 q + 512 k + 512 v
#define GU_N_  16384            // 8192 gate + 8192 up

// ---------------- scratch (device globals; no runtime allocation) ----------------
__device__ float g_xnorm[(size_t)M_ * H_];
__device__ float g_qkv[(size_t)M_ * QKV_N_];
__device__ float g_attn[(size_t)M_ * H_];
__device__ float g_h1[(size_t)M_ * H_];
__device__ float g_x2[(size_t)M_ * H_];
__device__ float g_gu[(size_t)M_ * GU_N_];
__device__ float g_act[(size_t)M_ * I_];
// tf32-converted weights
__device__ float w_qkv[(size_t)H_ * QKV_N_];
__device__ float w_o[(size_t)H_ * H_];
__device__ float w_gu[(size_t)H_ * GU_N_];
__device__ float w_dn[(size_t)I_ * H_];

// ---------------- helpers ----------------
__device__ __forceinline__ float to_tf32(float x) {
    uint32_t r;
    asm("cvt.rna.tf32.f32 %0, %1;" : "=r"(r) : "f"(x));
    return __uint_as_float(r);
}

__device__ __forceinline__ uint32_t smem_u32(const void* p) {
    return (uint32_t)__cvta_generic_to_shared(p);
}

__device__ __forceinline__ void cp_async16(uint32_t dst, const void* src) {
    asm volatile("cp.async.cg.shared.global [%0], [%1], 16;\n" :: "r"(dst), "l"(src));
}
__device__ __forceinline__ void cp_commit() { asm volatile("cp.async.commit_group;\n"); }
__device__ __forceinline__ void cp_wait0()  { asm volatile("cp.async.wait_group 0;\n"); }
__device__ __forceinline__ void cp_wait1()  { asm volatile("cp.async.wait_group 1;\n"); }

__device__ __forceinline__ void mma_tf32(float* d, const uint32_t* a, uint32_t b0, uint32_t b1) {
    asm volatile(
        "mma.sync.aligned.m16n8k8.row.col.f32.tf32.tf32.f32 "
        "{%0,%1,%2,%3}, {%4,%5,%6,%7}, {%8,%9}, {%0,%1,%2,%3};\n"
        : "+f"(d[0]), "+f"(d[1]), "+f"(d[2]), "+f"(d[3])
        : "r"(a[0]), "r"(a[1]), "r"(a[2]), "r"(a[3]), "r"(b0), "r"(b1));
}

// ---------------- weight convert (fp32 -> tf32) with column placement ----------------
__global__ void cvt2d_kernel(const float* __restrict__ src, float* __restrict__ dst,
                             int ncols4, int dstStride4, int colOff4, long total4) {
    long i = (long)blockIdx.x * blockDim.x + threadIdx.x;
    if (i >= total4) return;
    long r = i / ncols4;
    int c = (int)(i - r * ncols4);
    float4 v = ((const float4*)src)[i];
    v.x = to_tf32(v.x); v.y = to_tf32(v.y); v.z = to_tf32(v.z); v.w = to_tf32(v.w);
    ((float4*)dst)[r * (long)dstStride4 + colOff4 + c] = v;
}

// ---------------- RMSNorm, output tf32 ----------------
__global__ void rmsnorm_kernel(const float* __restrict__ x, const float* __restrict__ w,
                               float* __restrict__ y, int Hdim) {
    int row = blockIdx.x;
    const float4* xr = (const float4*)(x + (size_t)row * Hdim);
    float4* yr = (float4*)(y + (size_t)row * Hdim);
    const float4* wv = (const float4*)w;
    int n4 = Hdim >> 2;

    float ss = 0.f;
    for (int i = threadIdx.x; i < n4; i += blockDim.x) {
        float4 v = xr[i];
        ss += v.x * v.x + v.y * v.y + v.z * v.z + v.w * v.w;
    }
    __shared__ float wsum[8];
    for (int o = 16; o > 0; o >>= 1) ss += __shfl_xor_sync(0xffffffffu, ss, o);
    int warp = threadIdx.x >> 5;
    if ((threadIdx.x & 31) == 0) wsum[warp] = ss;
    __syncthreads();
    __shared__ float s_inv;
    if (threadIdx.x == 0) {
        float t = 0.f;
        #pragma unroll
        for (int i = 0; i < 8; i++) t += wsum[i];
        s_inv = rsqrtf(t / (float)Hdim + EPS_);
    }
    __syncthreads();
    float inv = s_inv;
    for (int i = threadIdx.x; i < n4; i += blockDim.x) {
        float4 v = xr[i];
        float4 ww = wv[i];
        float4 o;
        o.x = to_tf32(v.x * inv * ww.x); o.y = to_tf32(v.y * inv * ww.y);
        o.z = to_tf32(v.z * inv * ww.z); o.w = to_tf32(v.w * inv * ww.w);
        yr[i] = o;
    }
}

// ---------------- per-(token,head) RMSNorm + RoPE ----------------
__global__ void qknorm_rope_kernel(float* __restrict__ base, int rowStride,
                                   const float* __restrict__ w,
                                   const float* __restrict__ cosp, const float* __restrict__ sinp,
                                   int nheads) {
    int idx = blockIdx.x;
    int head = idx % nheads;
    int token = idx / nheads;
    float* p = base + (size_t)token * rowStride + head * DH_;
    int d = threadIdx.x;

    float v = p[d];
    float ss = v * v;
    for (int o = 16; o > 0; o >>= 1) ss += __shfl_xor_sync(0xffffffffu, ss, o);
    __shared__ float wsum[4];
    int warp = d >> 5;
    if ((d & 31) == 0) wsum[warp] = ss;
    __syncthreads();
    float tot = wsum[0] + wsum[1] + wsum[2] + wsum[3];
    float inv = rsqrtf(tot / (float)DH_ + EPS_);
    float vn = v * inv * w[d];

    __shared__ float sh[DH_];
    sh[d] = vn;
    __syncthreads();
    float other = (d < 64) ? -sh[d + 64] : sh[d - 64];
    float c = cosp[(size_t)token * DH_ + d];
    float s = sinp[(size_t)token * DH_ + d];
    p[d] = vn * c + other * s;
}

// ---------------- tf32 tensor-core GEMM: 256 thr, 8 warps, 3-stage cp.async ----------------
// 128x128x32 block tile, warp tile 64x32.
#define GPA 36
#define GPB 136
#define G_STAGE (128 * GPA + 32 * GPB)   // 8960 floats per stage

__device__ __forceinline__ void gemm_issue(const float* __restrict__ A, long K, long rowBase,
                                           const float* __restrict__ Bm, long N, long colBase,
                                           float* As, float* Bs, int tid, int k0) {
    // A: 128 rows x 32 k. thread t -> row t/2, half t%2 (16 floats = 4 cp16)
    {
        int r = tid >> 1, half = tid & 1;
        uint32_t dst = smem_u32(As + r * GPA + half * 16);
        const float* src = A + (rowBase + r) * K + k0 + half * 16;
        #pragma unroll
        for (int i = 0; i < 4; i++) cp_async16(dst + i * 16, src + i * 4);
    }
    // B: 32 k-rows x 128 cols = 1024 float4 chunks / 256 thr = 4 each
    #pragma unroll
    for (int p = 0; p < 4; p++) {
        int f = tid + p * 256;
        int kr = f >> 5, c4 = (f & 31) * 4;
        cp_async16(smem_u32(Bs + kr * GPB + c4),
                   Bm + (long)(k0 + kr) * N + colBase + c4);
    }
}

__device__ __forceinline__ void gemm_compute(const float* As, const float* Bs,
                                             int wm, int wn, int gid, int tig,
                                             float (&acc)[4][4][4]) {
    #pragma unroll
    for (int kk = 0; kk < 32; kk += 8) {
        uint32_t a[4][4];
        #pragma unroll
        for (int mi = 0; mi < 4; mi++) {
            const float* ap = As + (wm + mi * 16 + gid) * GPA;
            a[mi][0] = __float_as_uint(ap[kk + tig]);
            a[mi][1] = __float_as_uint(ap[8 * GPA + kk + tig]);
            a[mi][2] = __float_as_uint(ap[kk + tig + 4]);
            a[mi][3] = __float_as_uint(ap[8 * GPA + kk + tig + 4]);
        }
        #pragma unroll
        for (int ni = 0; ni < 4; ni++) {
            int col = wn + ni * 8 + gid;
            uint32_t b0 = __float_as_uint(Bs[(kk + tig) * GPB + col]);
            uint32_t b1 = __float_as_uint(Bs[(kk + tig + 4) * GPB + col]);
            #pragma unroll
            for (int mi = 0; mi < 4; mi++)
                mma_tf32(acc[mi][ni], a[mi], b0, b1);
        }
    }
}

__global__ __launch_bounds__(256, 2) void gemm_tf32(const float* __restrict__ A,
                                                    const float* __restrict__ Bm,
                                                    const float* __restrict__ Res,
                                                    float* __restrict__ C,
                                                    int M, int N, int K) {
    extern __shared__ float sm[];
    int tid = threadIdx.x;
    int wid = tid >> 5, lane = tid & 31;
    int gid = lane >> 2, tig = lane & 3;
    int wm = (wid >> 2) * 64, wn = (wid & 3) * 32;
    long rowBase = (long)blockIdx.y * 128;
    long colBase = (long)blockIdx.x * 128;

    float acc[4][4][4] = {};

    float* As[3] = { sm, sm + G_STAGE, sm + 2 * G_STAGE };
    float* Bs[3] = { sm + 128 * GPA, sm + G_STAGE + 128 * GPA, sm + 2 * G_STAGE + 128 * GPA };

    int nIter = K / 32;
    gemm_issue(A, K, rowBase, Bm, N, colBase, As[0], Bs[0], tid, 0);
    cp_commit();
    gemm_issue(A, K, rowBase, Bm, N, colBase, As[1], Bs[1], tid, 32);
    cp_commit();
    cp_wait1();
    __syncthreads();

    for (int it = 0; it < nIter; it++) {
        int buf = it % 3;
        if (it + 2 < nIter) {
            gemm_issue(A, K, rowBase, Bm, N, colBase, As[(it + 2) % 3], Bs[(it + 2) % 3],
                       tid, (it + 2) * 32);
            cp_commit();
        }
        gemm_compute(As[buf], Bs[buf], wm, wn, gid, tig, acc);
        if (it + 1 < nIter) {
            if (it + 2 < nIter) cp_wait1(); else cp_wait0();
            __syncthreads();
        }
    }

    #pragma unroll
    for (int mi = 0; mi < 4; mi++) {
        #pragma unroll
        for (int ni = 0; ni < 4; ni++) {
            long r0 = rowBase + wm + mi * 16 + gid;
            long c = colBase + wn + ni * 8 + tig * 2;
            float2 v0 = make_float2(acc[mi][ni][0], acc[mi][ni][1]);
            float2 v1 = make_float2(acc[mi][ni][2], acc[mi][ni][3]);
            if (Res != nullptr) {
                float2 r0v = *(const float2*)(Res + r0 * N + c);
                float2 r1v = *(const float2*)(Res + (r0 + 8) * N + c);
                v0.x += r0v.x; v0.y += r0v.y;
                v1.x += r1v.x; v1.y += r1v.y;
            }
            *(float2*)(C + r0 * N + c) = v0;
            *(float2*)(C + (r0 + 8) * N + c) = v1;
        }
    }
}

// ---------------- tensor-core flash attention (tf32 mma) ----------------
// Block: 128 q-rows, loops 32 kv-tiles of 64. 256 threads = 8 warps, warp = 16 q-rows.
// smem: Ks[64][132], Vs[64][136], Ps[128][76]  (Qs[128][132] aliases Ks+Vs during prologue)
#define KPAD 132
#define VPAD 136
#define PPAD 76
#define AT_SMEM_FLOATS (64 * KPAD + 64 * VPAD + 128 * PPAD)   // 26880

__global__ __launch_bounds__(256, 1) void attn_kernel(const float* __restrict__ qkv,
                                                      float* __restrict__ o) {
    extern __shared__ float sm[];
    float* Ks = sm;                       // 64 x 132
    float* Vs = sm + 64 * KPAD;           // 64 x 136
    float* Ps = sm + 64 * KPAD + 64 * VPAD; // 128 x 76
    float* Qs = sm;                       // 128 x 132 (prologue only, aliases Ks+Vs)

    int qb = blockIdx.x, h = blockIdx.y, b = blockIdx.z;
    int kvh = h / GROUPS_;
    int tid = threadIdx.x;
    int w = tid >> 5, lane = tid & 31;
    int gid = lane >> 2, tig = lane & 3;
    int wq = w * 16;
    long bS = (long)b * S_;

    const float scale = 0.08838834764831845f;  // 1/sqrt(128)

    // ---- prologue: Q tile -> smem (scaled, tf32), then per-warp A-fragments to regs
    for (int i = tid; i < 128 * 32; i += 256) {
        int r = i >> 5, c4 = (i & 31) * 4;
        const float* src = qkv + (bS + qb * 128 + r) * QKV_N_ + h * DH_ + c4;
        float4 v = *(const float4*)src;
        float* dst = Qs + r * KPAD + c4;
        dst[0] = to_tf32(v.x * scale); dst[1] = to_tf32(v.y * scale);
        dst[2] = to_tf32(v.z * scale); dst[3] = to_tf32(v.w * scale);
    }
    __syncthreads();
    uint32_t qf[16][4];
    #pragma unroll
    for (int kk = 0; kk < 16; kk++) {
        qf[kk][0] = __float_as_uint(Qs[(wq + gid) * KPAD + kk * 8 + tig]);
        qf[kk][1] = __float_as_uint(Qs[(wq + gid + 8) * KPAD + kk * 8 + tig]);
        qf[kk][2] = __float_as_uint(Qs[(wq + gid) * KPAD + kk * 8 + tig + 4]);
        qf[kk][3] = __float_as_uint(Qs[(wq + gid + 8) * KPAD + kk * 8 + tig + 4]);
    }
    __syncthreads();

    float of[16][4] = {};
    float m0 = -INFINITY, m1 = -INFINITY, l0 = 0.f, l1 = 0.f;

    for (int kt = 0; kt < S_ / 64; kt++) {
        // ---- fill K,V tiles (tf32)
        for (int i = tid; i < 64 * 32; i += 256) {
            int r = i >> 5, c4 = (i & 31) * 4;
            long gb = (bS + kt * 64 + r) * QKV_N_ + kvh * DH_ + c4;
            float4 kv = *(const float4*)(qkv + 2048 + gb);
            float* kd = Ks + r * KPAD + c4;
            kd[0] = to_tf32(kv.x); kd[1] = to_tf32(kv.y);
            kd[2] = to_tf32(kv.z); kd[3] = to_tf32(kv.w);
            float4 vv = *(const float4*)(qkv + 2560 + gb);
            float* vd = Vs + r * VPAD + c4;
            vd[0] = to_tf32(vv.x); vd[1] = to_tf32(vv.y);
            vd[2] = to_tf32(vv.z); vd[3] = to_tf32(vv.w);
        }
        __syncthreads();

        // ---- scores: S[16 x 64] per warp = Q @ K^T
        float sc[8][4] = {};
        #pragma unroll
        for (int kk = 0; kk < 16; kk++) {
            #pragma unroll
            for (int ni = 0; ni < 8; ni++) {
                uint32_t b0 = __float_as_uint(Ks[(ni * 8 + gid) * KPAD + kk * 8 + tig]);
                uint32_t b1 = __float_as_uint(Ks[(ni * 8 + gid) * KPAD + kk * 8 + tig + 4]);
                mma_tf32(sc[ni], qf[kk], b0, b1);
            }
        }

        // ---- online softmax (rows gid and gid+8)
        float mx0 = -INFINITY, mx1 = -INFINITY;
        #pragma unroll
        for (int ni = 0; ni < 8; ni++) {
            mx0 = fmaxf(mx0, fmaxf(sc[ni][0], sc[ni][1]));
            mx1 = fmaxf(mx1, fmaxf(sc[ni][2], sc[ni][3]));
        }
        mx0 = fmaxf(mx0, __shfl_xor_sync(0xffffffffu, mx0, 1));
        mx0 = fmaxf(mx0, __shfl_xor_sync(0xffffffffu, mx0, 2));
        mx1 = fmaxf(mx1, __shfl_xor_sync(0xffffffffu, mx1, 1));
        mx1 = fmaxf(mx1, __shfl_xor_sync(0xffffffffu, mx1, 2));
        float nm0 = fmaxf(m0, mx0), nm1 = fmaxf(m1, mx1);
        float s0 = 0.f, s1 = 0.f;
        #pragma unroll
        for (int ni = 0; ni < 8; ni++) {
            float e0 = to_tf32(__expf(sc[ni][0] - nm0));
            float e1 = to_tf32(__expf(sc[ni][1] - nm0));
            float e2 = to_tf32(__expf(sc[ni][2] - nm1));
            float e3 = to_tf32(__expf(sc[ni][3] - nm1));
            s0 += e0 + e1; s1 += e2 + e3;
            *(float2*)(Ps + (wq + gid) * PPAD + ni * 8 + tig * 2) = make_float2(e0, e1);
            *(float2*)(Ps + (wq + gid + 8) * PPAD + ni * 8 + tig * 2) = make_float2(e2, e3);
        }
        s0 += __shfl_xor_sync(0xffffffffu, s0, 1);
        s0 += __shfl_xor_sync(0xffffffffu, s0, 2);
        s1 += __shfl_xor_sync(0xffffffffu, s1, 1);
        s1 += __shfl_xor_sync(0xffffffffu, s1, 2);
        float a0 = __expf(m0 - nm0), a1 = __expf(m1 - nm1);
        l0 = l0 * a0 + s0; l1 = l1 * a1 + s1;
        m0 = nm0; m1 = nm1;
        #pragma unroll
        for (int ni = 0; ni < 16; ni++) {
            of[ni][0] *= a0; of[ni][1] *= a0;
            of[ni][2] *= a1; of[ni][3] *= a1;
        }
        __syncwarp();

        // ---- O += P @ V
        #pragma unroll
        for (int kkj = 0; kkj < 8; kkj++) {
            uint32_t pa[4];
            pa[0] = __float_as_uint(Ps[(wq + gid) * PPAD + kkj * 8 + tig]);
            pa[1] = __float_as_uint(Ps[(wq + gid + 8) * PPAD + kkj * 8 + tig]);
            pa[2] = __float_as_uint(Ps[(wq + gid) * PPAD + kkj * 8 + tig + 4]);
            pa[3] = __float_as_uint(Ps[(wq + gid + 8) * PPAD + kkj * 8 + tig + 4]);
            #pragma unroll
            for (int ni = 0; ni < 16; ni++) {
                uint32_t b0 = __float_as_uint(Vs[(kkj * 8 + tig) * VPAD + ni * 8 + gid]);
                uint32_t b1 = __float_as_uint(Vs[(kkj * 8 + tig + 4) * VPAD + ni * 8 + gid]);
                mma_tf32(of[ni], pa, b0, b1);
            }
        }
        __syncthreads();
    }

    // ---- epilogue: normalize, write (b,s,h,d) as tf32
    float inv0 = 1.f / l0, inv1 = 1.f / l1;
    long r0 = bS + qb * 128 + wq + gid;
    long r1 = r0 + 8;
    #pragma unroll
    for (int ni = 0; ni < 16; ni++) {
        int d = ni * 8 + tig * 2;
        float2 v0 = make_float2(to_tf32(of[ni][0] * inv0), to_tf32(of[ni][1] * inv0));
        float2 v1 = make_float2(to_tf32(of[ni][2] * inv1), to_tf32(of[ni][3] * inv1));
        *(float2*)(o + (r0 * NH_ + h) * DH_ + d) = v0;
        *(float2*)(o + (r1 * NH_ + h) * DH_ + d) = v1;
    }
}

// ---------------- silu(gate) * up from fused gu buffer, tf32 output ----------------
__global__ void silu_mul_kernel(const float* __restrict__ gu, float* __restrict__ out, long total4) {
    long i = (long)blockIdx.x * blockDim.x + threadIdx.x;
    if (i >= total4) return;
    long mrow = i >> 11;
    int c4 = (int)(i & 2047);
    const float4* gu4 = (const float4*)gu;
    float4 gv = gu4[mrow * 4096 + c4];
    float4 uv = gu4[mrow * 4096 + 2048 + c4];
    float4 o;
    o.x = to_tf32(gv.x / (1.f + __expf(-gv.x)) * uv.x);
    o.y = to_tf32(gv.y / (1.f + __expf(-gv.y)) * uv.y);
    o.z = to_tf32(gv.z / (1.f + __expf(-gv.z)) * uv.z);
    o.w = to_tf32(gv.w / (1.f + __expf(-gv.w)) * uv.w);
    ((float4*)out)[i] = o;
}

// ---------------- launch ----------------
static inline void launch_cvt(const float* src, float* dst, int ncols4, int stride4, int off4, long total4) {
    int blocks = (int)((total4 + 255) / 256);
    cvt2d_kernel<<<blocks, 256>>>(src, dst, ncols4, stride4, off4, total4);
}

extern "C" void kernel_launch(void* const* d_in, const int* in_sizes, int n_in,
                              void* d_out, int out_size) {
    const float* hidden = (const float*)d_in[0];
    const float* cosp   = (const float*)d_in[1];
    const float* sinp   = (const float*)d_in[2];
    const float* wq     = (const float*)d_in[3];
    const float* wk     = (const float*)d_in[4];
    const float* wv     = (const float*)d_in[5];
    const float* wo     = (const float*)d_in[6];
    const float* qnw    = (const float*)d_in[7];
    const float* knw    = (const float*)d_in[8];
    const float* anw    = (const float*)d_in[9];
    const float* mnw    = (const float*)d_in[10];
    const float* wgate  = (const float*)d_in[11];
    const float* wup    = (const float*)d_in[12];
    const float* wdown  = (const float*)d_in[13];
    float* out = (float*)d_out;

    float *xnorm, *qkv, *attn, *h1, *x2, *gu, *act;
    float *Wqkv, *Wo, *Wgu, *Wdn;
    cudaGetSymbolAddress((void**)&xnorm, g_xnorm);
    cudaGetSymbolAddress((void**)&qkv, g_qkv);
    cudaGetSymbolAddress((void**)&attn, g_attn);
    cudaGetSymbolAddress((void**)&h1, g_h1);
    cudaGetSymbolAddress((void**)&x2, g_x2);
    cudaGetSymbolAddress((void**)&gu, g_gu);
    cudaGetSymbolAddress((void**)&act, g_act);
    cudaGetSymbolAddress((void**)&Wqkv, w_qkv);
    cudaGetSymbolAddress((void**)&Wo, w_o);
    cudaGetSymbolAddress((void**)&Wgu, w_gu);
    cudaGetSymbolAddress((void**)&Wdn, w_dn);

    const int attn_smem = AT_SMEM_FLOATS * sizeof(float);
    cudaFuncSetAttribute(attn_kernel, cudaFuncAttributeMaxDynamicSharedMemorySize, attn_smem);
    const int gemm_smem = 3 * G_STAGE * sizeof(float);
    cudaFuncSetAttribute(gemm_tf32, cudaFuncAttributeMaxDynamicSharedMemorySize, gemm_smem);

    // 0) convert weights to tf32 (fused/concatenated layouts)
    launch_cvt(wq,    Wqkv, 512,  768,  0,    (long)H_ * 512);
    launch_cvt(wk,    Wqkv, 128,  768,  512,  (long)H_ * 128);
    launch_cvt(wv,    Wqkv, 128,  768,  640,  (long)H_ * 128);
    launch_cvt(wo,    Wo,   512,  512,  0,    (long)H_ * 512);
    launch_cvt(wgate, Wgu,  2048, 4096, 0,    (long)H_ * 2048);
    launch_cvt(wup,   Wgu,  2048, 4096, 2048, (long)H_ * 2048);
    launch_cvt(wdown, Wdn,  512,  512,  0,    (long)I_ * 512);

    // 1) attn rmsnorm (tf32 out)
    rmsnorm_kernel<<<M_, 256>>>(hidden, anw, xnorm, H_);

    // 2) fused QKV projection
    gemm_tf32<<<dim3(QKV_N_ / 128, M_ / 128), 256, gemm_smem>>>(xnorm, Wqkv, nullptr, qkv, M_, QKV_N_, H_);

    // 3) q/k norm + rope (in place in qkv buffer, fp32 out)
    qknorm_rope_kernel<<<M_ * NH_, DH_>>>(qkv, QKV_N_, qnw, cosp, sinp, NH_);
    qknorm_rope_kernel<<<M_ * NKV_, DH_>>>(qkv + 2048, QKV_N_, knw, cosp, sinp, NKV_);

    // 4) attention (tensor cores, tf32; tf32 out)
    attn_kernel<<<dim3(S_ / 128, NH_, B_), 256, attn_smem>>>(qkv, attn);

    // 5) O projection + residual
    gemm_tf32<<<dim3(H_ / 128, M_ / 128), 256, gemm_smem>>>(attn, Wo, hidden, h1, M_, H_, NH_ * DH_);

    // 6) mlp rmsnorm (tf32 out)
    rmsnorm_kernel<<<M_, 256>>>(h1, mnw, x2, H_);

    // 7) fused gate+up projection
    gemm_tf32<<<dim3(GU_N_ / 128, M_ / 128), 256, gemm_smem>>>(x2, Wgu, nullptr, gu, M_, GU_N_, H_);

    // 8) silu * up (tf32 out)
    {
        long total4 = (long)M_ * I_ / 4;
        int blocks = (int)((total4 + 255) / 256);
        silu_mul_kernel<<<blocks, 256>>>(gu, act, total4);
    }

    // 9) down projection + residual -> output
    gemm_tf32<<<dim3(H_ / 128, M_ / 128), 256, gemm_smem>>>(act, Wdn, h1, out, M_, H_, I_);
}

// round 7
// speedup vs baseline: 2.3258x; 1.0099x over previous
#include <cuda_runtime.h>
#include <cuda_bf16.h>
#include <math.h>
#include <stdint.h>

#define B_   2
#define S_   2048
#define H_   2048
#define NH_  16
#define NKV_ 4
#define DH_  128
#define I_   8192
#define M_   (B_ * S_)          // 4096 tokens
#define GROUPS_ (NH_ / NKV_)    // 4
#define EPS_ 1e-6f

#define QKV_N_ 3072             // 2048 q + 512 k + 512 v
#define GU_N_  16384            // 8192 gate + 8192 up

// ---------------- scratch (device globals; no runtime allocation) ----------------
__device__ float g_xnorm[(size_t)M_ * H_];
__device__ float g_qkv[(size_t)M_ * QKV_N_];
__device__ float g_attn[(size_t)M_ * H_];
__device__ float g_h1[(size_t)M_ * H_];
__device__ float g_x2[(size_t)M_ * H_];
__device__ float g_gu[(size_t)M_ * GU_N_];
__device__ float g_act[(size_t)M_ * I_];
// tf32-converted weights, [K][N] row-major (same as source layout)
__device__ float w_qkv[(size_t)H_ * QKV_N_];
__device__ float w_o[(size_t)H_ * H_];
__device__ float w_gu[(size_t)H_ * GU_N_];
__device__ float w_dn[(size_t)I_ * H_];

// ---------------- helpers ----------------
__device__ __forceinline__ float to_tf32(float x) {
    uint32_t r;
    asm("cvt.rna.tf32.f32 %0, %1;" : "=r"(r) : "f"(x));
    return __uint_as_float(r);
}

__device__ __forceinline__ uint32_t smem_u32(const void* p) {
    return (uint32_t)__cvta_generic_to_shared(p);
}

__device__ __forceinline__ void cp_async16(uint32_t dst, const void* src) {
    asm volatile("cp.async.cg.shared.global [%0], [%1], 16;\n" :: "r"(dst), "l"(src));
}
__device__ __forceinline__ void cp_commit() { asm volatile("cp.async.commit_group;\n"); }
__device__ __forceinline__ void cp_wait0()  { asm volatile("cp.async.wait_group 0;\n"); }
__device__ __forceinline__ void cp_wait1()  { asm volatile("cp.async.wait_group 1;\n"); }
__device__ __forceinline__ void cp_wait2()  { asm volatile("cp.async.wait_group 2;\n"); }

__device__ __forceinline__ void mma_tf32(float* d, const uint32_t* a, uint32_t b0, uint32_t b1) {
    asm volatile(
        "mma.sync.aligned.m16n8k8.row.col.f32.tf32.tf32.f32 "
        "{%0,%1,%2,%3}, {%4,%5,%6,%7}, {%8,%9}, {%0,%1,%2,%3};\n"
        : "+f"(d[0]), "+f"(d[1]), "+f"(d[2]), "+f"(d[3])
        : "r"(a[0]), "r"(a[1]), "r"(a[2]), "r"(a[3]), "r"(b0), "r"(b1));
}

// ---------------- weight convert (fp32 -> tf32) with column placement ----------------
__global__ void cvt2d_kernel(const float* __restrict__ src, float* __restrict__ dst,
                             int ncols4, int dstStride4, int colOff4, long total4) {
    long i = (long)blockIdx.x * blockDim.x + threadIdx.x;
    if (i >= total4) return;
    long r = i / ncols4;
    int c = (int)(i - r * ncols4);
    float4 v = ((const float4*)src)[i];
    v.x = to_tf32(v.x); v.y = to_tf32(v.y); v.z = to_tf32(v.z); v.w = to_tf32(v.w);
    ((float4*)dst)[r * (long)dstStride4 + colOff4 + c] = v;
}

// ---------------- RMSNorm, output tf32 ----------------
__global__ void rmsnorm_kernel(const float* __restrict__ x, const float* __restrict__ w,
                               float* __restrict__ y, int Hdim) {
    int row = blockIdx.x;
    const float4* xr = (const float4*)(x + (size_t)row * Hdim);
    float4* yr = (float4*)(y + (size_t)row * Hdim);
    const float4* wv = (const float4*)w;
    int n4 = Hdim >> 2;

    float ss = 0.f;
    for (int i = threadIdx.x; i < n4; i += blockDim.x) {
        float4 v = xr[i];
        ss += v.x * v.x + v.y * v.y + v.z * v.z + v.w * v.w;
    }
    __shared__ float wsum[8];
    for (int o = 16; o > 0; o >>= 1) ss += __shfl_xor_sync(0xffffffffu, ss, o);
    int warp = threadIdx.x >> 5;
    if ((threadIdx.x & 31) == 0) wsum[warp] = ss;
    __syncthreads();
    __shared__ float s_inv;
    if (threadIdx.x == 0) {
        float t = 0.f;
        #pragma unroll
        for (int i = 0; i < 8; i++) t += wsum[i];
        s_inv = rsqrtf(t / (float)Hdim + EPS_);
    }
    __syncthreads();
    float inv = s_inv;
    for (int i = threadIdx.x; i < n4; i += blockDim.x) {
        float4 v = xr[i];
        float4 ww = wv[i];
        float4 o;
        o.x = to_tf32(v.x * inv * ww.x); o.y = to_tf32(v.y * inv * ww.y);
        o.z = to_tf32(v.z * inv * ww.z); o.w = to_tf32(v.w * inv * ww.w);
        yr[i] = o;
    }
}

// ---------------- per-(token,head) RMSNorm + RoPE ----------------
__global__ void qknorm_rope_kernel(float* __restrict__ base, int rowStride,
                                   const float* __restrict__ w,
                                   const float* __restrict__ cosp, const float* __restrict__ sinp,
                                   int nheads) {
    int idx = blockIdx.x;
    int head = idx % nheads;
    int token = idx / nheads;
    float* p = base + (size_t)token * rowStride + head * DH_;
    int d = threadIdx.x;

    float v = p[d];
    float ss = v * v;
    for (int o = 16; o > 0; o >>= 1) ss += __shfl_xor_sync(0xffffffffu, ss, o);
    __shared__ float wsum[4];
    int warp = d >> 5;
    if ((d & 31) == 0) wsum[warp] = ss;
    __syncthreads();
    float tot = wsum[0] + wsum[1] + wsum[2] + wsum[3];
    float inv = rsqrtf(tot / (float)DH_ + EPS_);
    float vn = v * inv * w[d];

    __shared__ float sh[DH_];
    sh[d] = vn;
    __syncthreads();
    float other = (d < 64) ? -sh[d + 64] : sh[d - 64];
    float c = cosp[(size_t)token * DH_ + d];
    float s = sinp[(size_t)token * DH_ + d];
    p[d] = vn * c + other * s;
}

// ---------------- tf32 tensor-core GEMM: 256 thr, 8 warps, 4-stage cp.async ----------------
// 128x256x32 block tile, warp tile 64x64 (warps in 2x4 grid).
#define GPA 36
#define GPB 264
#define G_STAGE (128 * GPA + 32 * GPB)   // 13056 floats = 52224 B per stage
#define G_NSTAGE 4

__device__ __forceinline__ void gemm_issue(const float* __restrict__ A, long K, long rowBase,
                                           const float* __restrict__ Bm, long N, long colBase,
                                           float* As, float* Bs, int tid, int k0) {
    // A: 128 rows x 32 k. thread t -> row t/2, half t%2 (16 floats = 4 cp16)
    {
        int r = tid >> 1, half = tid & 1;
        uint32_t dst = smem_u32(As + r * GPA + half * 16);
        const float* src = A + (rowBase + r) * K + k0 + half * 16;
        #pragma unroll
        for (int i = 0; i < 4; i++) cp_async16(dst + i * 16, src + i * 4);
    }
    // B: 32 k-rows x 256 cols = 2048 float4 chunks / 256 thr = 8 each
    #pragma unroll
    for (int p = 0; p < 8; p++) {
        int f = tid + p * 256;
        int kr = f >> 6, c4 = (f & 63) * 4;
        cp_async16(smem_u32(Bs + kr * GPB + c4),
                   Bm + (long)(k0 + kr) * N + colBase + c4);
    }
}

__device__ __forceinline__ void gemm_compute(const float* As, const float* Bs,
                                             int wm, int wn, int gid, int tig,
                                             float (&acc)[4][8][4]) {
    #pragma unroll
    for (int kk = 0; kk < 32; kk += 8) {
        uint32_t a[4][4];
        #pragma unroll
        for (int mi = 0; mi < 4; mi++) {
            const float* ap = As + (wm + mi * 16 + gid) * GPA;
            a[mi][0] = __float_as_uint(ap[kk + tig]);
            a[mi][1] = __float_as_uint(ap[8 * GPA + kk + tig]);
            a[mi][2] = __float_as_uint(ap[kk + tig + 4]);
            a[mi][3] = __float_as_uint(ap[8 * GPA + kk + tig + 4]);
        }
        #pragma unroll
        for (int ni = 0; ni < 8; ni++) {
            int col = wn + ni * 8 + gid;
            uint32_t b0 = __float_as_uint(Bs[(kk + tig) * GPB + col]);
            uint32_t b1 = __float_as_uint(Bs[(kk + tig + 4) * GPB + col]);
            #pragma unroll
            for (int mi = 0; mi < 4; mi++)
                mma_tf32(acc[mi][ni], a[mi], b0, b1);
        }
    }
}

__global__ __launch_bounds__(256, 1) void gemm_tf32(const float* __restrict__ A,
                                                    const float* __restrict__ Bm,
                                                    const float* __restrict__ Res,
                                                    float* __restrict__ C,
                                                    int Mdim, int N, int K) {
    extern __shared__ float sm[];
    int tid = threadIdx.x;
    int wid = tid >> 5, lane = tid & 31;
    int gid = lane >> 2, tig = lane & 3;
    int wm = (wid >> 2) * 64, wn = (wid & 3) * 64;
    long rowBase = (long)blockIdx.y * 128;
    long colBase = (long)blockIdx.x * 256;

    float acc[4][8][4] = {};

    float* As[G_NSTAGE];
    float* Bs[G_NSTAGE];
    #pragma unroll
    for (int s = 0; s < G_NSTAGE; s++) {
        As[s] = sm + s * G_STAGE;
        Bs[s] = As[s] + 128 * GPA;
    }

    int nIter = K / 32;
    // prologue: fill 3 stages
    #pragma unroll
    for (int s = 0; s < 3; s++) {
        gemm_issue(A, K, rowBase, Bm, N, colBase, As[s], Bs[s], tid, s * 32);
        cp_commit();
    }

    for (int it = 0; it < nIter; it++) {
        // wait for stage `it` to land (tail-aware group counting)
        if (it + 2 < nIter) cp_wait2();
        else if (it + 1 < nIter) cp_wait1();
        else cp_wait0();
        __syncthreads();   // all warps see stage `it`; all warps done with stage `it-1`

        if (it + 3 < nIter) {  // refill the buffer consumed at it-1
            gemm_issue(A, K, rowBase, Bm, N, colBase,
                       As[(it + 3) & 3], Bs[(it + 3) & 3], tid, (it + 3) * 32);
            cp_commit();
        }

        gemm_compute(As[it & 3], Bs[it & 3], wm, wn, gid, tig, acc);
    }

    // epilogue
    #pragma unroll
    for (int mi = 0; mi < 4; mi++) {
        #pragma unroll
        for (int ni = 0; ni < 8; ni++) {
            long r0 = rowBase + wm + mi * 16 + gid;
            long c = colBase + wn + ni * 8 + tig * 2;
            float2 v0 = make_float2(acc[mi][ni][0], acc[mi][ni][1]);
            float2 v1 = make_float2(acc[mi][ni][2], acc[mi][ni][3]);
            if (Res != nullptr) {
                float2 r0v = *(const float2*)(Res + r0 * N + c);
                float2 r1v = *(const float2*)(Res + (r0 + 8) * N + c);
                v0.x += r0v.x; v0.y += r0v.y;
                v1.x += r1v.x; v1.y += r1v.y;
            }
            *(float2*)(C + r0 * N + c) = v0;
            *(float2*)(C + (r0 + 8) * N + c) = v1;
        }
    }
}
#define GEMM_SMEM_BYTES (G_NSTAGE * G_STAGE * (int)sizeof(float))

// ---------------- tensor-core flash attention (tf32 mma.sync) ----------------
#define KPAD 132
#define VPAD 136
#define PPAD 76
#define AT_SMEM_FLOATS (64 * KPAD + 64 * VPAD + 128 * PPAD)   // 26880

__global__ __launch_bounds__(256, 1) void attn_kernel(const float* __restrict__ qkv,
                                                      float* __restrict__ o) {
    extern __shared__ float sm[];
    float* Ks = sm;                         // 64 x 132
    float* Vs = sm + 64 * KPAD;             // 64 x 136
    float* Ps = sm + 64 * KPAD + 64 * VPAD; // 128 x 76
    float* Qs = sm;                         // 128 x 132 (prologue only)

    int qb = blockIdx.x, h = blockIdx.y, b = blockIdx.z;
    int kvh = h / GROUPS_;
    int tid = threadIdx.x;
    int w = tid >> 5, lane = tid & 31;
    int gid = lane >> 2, tig = lane & 3;
    int wq = w * 16;
    long bS = (long)b * S_;

    const float scale = 0.08838834764831845f;

    for (int i = tid; i < 128 * 32; i += 256) {
        int r = i >> 5, c4 = (i & 31) * 4;
        const float* src = qkv + (bS + qb * 128 + r) * QKV_N_ + h * DH_ + c4;
        float4 v = *(const float4*)src;
        float* dst = Qs + r * KPAD + c4;
        dst[0] = to_tf32(v.x * scale); dst[1] = to_tf32(v.y * scale);
        dst[2] = to_tf32(v.z * scale); dst[3] = to_tf32(v.w * scale);
    }
    __syncthreads();
    uint32_t qf[16][4];
    #pragma unroll
    for (int kk = 0; kk < 16; kk++) {
        qf[kk][0] = __float_as_uint(Qs[(wq + gid) * KPAD + kk * 8 + tig]);
        qf[kk][1] = __float_as_uint(Qs[(wq + gid + 8) * KPAD + kk * 8 + tig]);
        qf[kk][2] = __float_as_uint(Qs[(wq + gid) * KPAD + kk * 8 + tig + 4]);
        qf[kk][3] = __float_as_uint(Qs[(wq + gid + 8) * KPAD + kk * 8 + tig + 4]);
    }
    __syncthreads();

    float of[16][4] = {};
    float m0 = -INFINITY, m1 = -INFINITY, l0 = 0.f, l1 = 0.f;

    for (int kt = 0; kt < S_ / 64; kt++) {
        for (int i = tid; i < 64 * 32; i += 256) {
            int r = i >> 5, c4 = (i & 31) * 4;
            long gb = (bS + kt * 64 + r) * QKV_N_ + kvh * DH_ + c4;
            float4 kv = *(const float4*)(qkv + 2048 + gb);
            float* kd = Ks + r * KPAD + c4;
            kd[0] = to_tf32(kv.x); kd[1] = to_tf32(kv.y);
            kd[2] = to_tf32(kv.z); kd[3] = to_tf32(kv.w);
            float4 vv = *(const float4*)(qkv + 2560 + gb);
            float* vd = Vs + r * VPAD + c4;
            vd[0] = to_tf32(vv.x); vd[1] = to_tf32(vv.y);
            vd[2] = to_tf32(vv.z); vd[3] = to_tf32(vv.w);
        }
        __syncthreads();

        float sc[8][4] = {};
        #pragma unroll
        for (int kk = 0; kk < 16; kk++) {
            #pragma unroll
            for (int ni = 0; ni < 8; ni++) {
                uint32_t b0 = __float_as_uint(Ks[(ni * 8 + gid) * KPAD + kk * 8 + tig]);
                uint32_t b1 = __float_as_uint(Ks[(ni * 8 + gid) * KPAD + kk * 8 + tig + 4]);
                mma_tf32(sc[ni], qf[kk], b0, b1);
            }
        }

        float mx0 = -INFINITY, mx1 = -INFINITY;
        #pragma unroll
        for (int ni = 0; ni < 8; ni++) {
            mx0 = fmaxf(mx0, fmaxf(sc[ni][0], sc[ni][1]));
            mx1 = fmaxf(mx1, fmaxf(sc[ni][2], sc[ni][3]));
        }
        mx0 = fmaxf(mx0, __shfl_xor_sync(0xffffffffu, mx0, 1));
        mx0 = fmaxf(mx0, __shfl_xor_sync(0xffffffffu, mx0, 2));
        mx1 = fmaxf(mx1, __shfl_xor_sync(0xffffffffu, mx1, 1));
        mx1 = fmaxf(mx1, __shfl_xor_sync(0xffffffffu, mx1, 2));
        float nm0 = fmaxf(m0, mx0), nm1 = fmaxf(m1, mx1);
        float s0 = 0.f, s1 = 0.f;
        #pragma unroll
        for (int ni = 0; ni < 8; ni++) {
            float e0 = to_tf32(__expf(sc[ni][0] - nm0));
            float e1 = to_tf32(__expf(sc[ni][1] - nm0));
            float e2 = to_tf32(__expf(sc[ni][2] - nm1));
            float e3 = to_tf32(__expf(sc[ni][3] - nm1));
            s0 += e0 + e1; s1 += e2 + e3;
            *(float2*)(Ps + (wq + gid) * PPAD + ni * 8 + tig * 2) = make_float2(e0, e1);
            *(float2*)(Ps + (wq + gid + 8) * PPAD + ni * 8 + tig * 2) = make_float2(e2, e3);
        }
        s0 += __shfl_xor_sync(0xffffffffu, s0, 1);
        s0 += __shfl_xor_sync(0xffffffffu, s0, 2);
        s1 += __shfl_xor_sync(0xffffffffu, s1, 1);
        s1 += __shfl_xor_sync(0xffffffffu, s1, 2);
        float a0 = __expf(m0 - nm0), a1 = __expf(m1 - nm1);
        l0 = l0 * a0 + s0; l1 = l1 * a1 + s1;
        m0 = nm0; m1 = nm1;
        #pragma unroll
        for (int ni = 0; ni < 16; ni++) {
            of[ni][0] *= a0; of[ni][1] *= a0;
            of[ni][2] *= a1; of[ni][3] *= a1;
        }
        __syncwarp();

        #pragma unroll
        for (int kkj = 0; kkj < 8; kkj++) {
            uint32_t pa[4];
            pa[0] = __float_as_uint(Ps[(wq + gid) * PPAD + kkj * 8 + tig]);
            pa[1] = __float_as_uint(Ps[(wq + gid + 8) * PPAD + kkj * 8 + tig]);
            pa[2] = __float_as_uint(Ps[(wq + gid) * PPAD + kkj * 8 + tig + 4]);
            pa[3] = __float_as_uint(Ps[(wq + gid + 8) * PPAD + kkj * 8 + tig + 4]);
            #pragma unroll
            for (int ni = 0; ni < 16; ni++) {
                uint32_t b0 = __float_as_uint(Vs[(kkj * 8 + tig) * VPAD + ni * 8 + gid]);
                uint32_t b1 = __float_as_uint(Vs[(kkj * 8 + tig + 4) * VPAD + ni * 8 + gid]);
                mma_tf32(of[ni], pa, b0, b1);
            }
        }
        __syncthreads();
    }

    float inv0 = 1.f / l0, inv1 = 1.f / l1;
    long r0 = bS + qb * 128 + wq + gid;
    long r1 = r0 + 8;
    #pragma unroll
    for (int ni = 0; ni < 16; ni++) {
        int d = ni * 8 + tig * 2;
        float2 v0 = make_float2(to_tf32(of[ni][0] * inv0), to_tf32(of[ni][1] * inv0));
        float2 v1 = make_float2(to_tf32(of[ni][2] * inv1), to_tf32(of[ni][3] * inv1));
        *(float2*)(o + (r0 * NH_ + h) * DH_ + d) = v0;
        *(float2*)(o + (r1 * NH_ + h) * DH_ + d) = v1;
    }
}

// ---------------- silu(gate) * up, tf32 output ----------------
__global__ void silu_mul_kernel(const float* __restrict__ gu, float* __restrict__ out, long total4) {
    long i = (long)blockIdx.x * blockDim.x + threadIdx.x;
    if (i >= total4) return;
    long mrow = i >> 11;
    int c4 = (int)(i & 2047);
    const float4* gu4 = (const float4*)gu;
    float4 gv = gu4[mrow * 4096 + c4];
    float4 uv = gu4[mrow * 4096 + 2048 + c4];
    float4 o;
    o.x = to_tf32(gv.x / (1.f + __expf(-gv.x)) * uv.x);
    o.y = to_tf32(gv.y / (1.f + __expf(-gv.y)) * uv.y);
    o.z = to_tf32(gv.z / (1.f + __expf(-gv.z)) * uv.z);
    o.w = to_tf32(gv.w / (1.f + __expf(-gv.w)) * uv.w);
    ((float4*)out)[i] = o;
}

// ---------------- launch ----------------
static inline void launch_cvt(const float* src, float* dst, int ncols4, int stride4, int off4, long total4) {
    int blocks = (int)((total4 + 255) / 256);
    cvt2d_kernel<<<blocks, 256>>>(src, dst, ncols4, stride4, off4, total4);
}

extern "C" void kernel_launch(void* const* d_in, const int* in_sizes, int n_in,
                              void* d_out, int out_size) {
    const float* hidden = (const float*)d_in[0];
    const float* cosp   = (const float*)d_in[1];
    const float* sinp   = (const float*)d_in[2];
    const float* wq     = (const float*)d_in[3];
    const float* wk     = (const float*)d_in[4];
    const float* wv     = (const float*)d_in[5];
    const float* wo     = (const float*)d_in[6];
    const float* qnw    = (const float*)d_in[7];
    const float* knw    = (const float*)d_in[8];
    const float* anw    = (const float*)d_in[9];
    const float* mnw    = (const float*)d_in[10];
    const float* wgate  = (const float*)d_in[11];
    const float* wup    = (const float*)d_in[12];
    const float* wdown  = (const float*)d_in[13];
    float* out = (float*)d_out;

    float *xnorm, *qkv, *attn, *h1, *x2, *gu, *act;
    float *Wqkv, *Wo, *Wgu, *Wdn;
    cudaGetSymbolAddress((void**)&xnorm, g_xnorm);
    cudaGetSymbolAddress((void**)&qkv, g_qkv);
    cudaGetSymbolAddress((void**)&attn, g_attn);
    cudaGetSymbolAddress((void**)&h1, g_h1);
    cudaGetSymbolAddress((void**)&x2, g_x2);
    cudaGetSymbolAddress((void**)&gu, g_gu);
    cudaGetSymbolAddress((void**)&act, g_act);
    cudaGetSymbolAddress((void**)&Wqkv, w_qkv);
    cudaGetSymbolAddress((void**)&Wo, w_o);
    cudaGetSymbolAddress((void**)&Wgu, w_gu);
    cudaGetSymbolAddress((void**)&Wdn, w_dn);

    const int attn_smem = AT_SMEM_FLOATS * sizeof(float);
    cudaFuncSetAttribute(attn_kernel, cudaFuncAttributeMaxDynamicSharedMemorySize, attn_smem);
    cudaFuncSetAttribute(gemm_tf32, cudaFuncAttributeMaxDynamicSharedMemorySize, GEMM_SMEM_BYTES);

    // 0) convert weights to tf32 (fused/concatenated layouts, [K][N])
    launch_cvt(wq,    Wqkv, 512,  768,  0,    (long)H_ * 512);
    launch_cvt(wk,    Wqkv, 128,  768,  512,  (long)H_ * 128);
    launch_cvt(wv,    Wqkv, 128,  768,  640,  (long)H_ * 128);
    launch_cvt(wo,    Wo,   512,  512,  0,    (long)H_ * 512);
    launch_cvt(wgate, Wgu,  2048, 4096, 0,    (long)H_ * 2048);
    launch_cvt(wup,   Wgu,  2048, 4096, 2048, (long)H_ * 2048);
    launch_cvt(wdown, Wdn,  512,  512,  0,    (long)I_ * 512);

    // 1) attn rmsnorm (tf32 out)
    rmsnorm_kernel<<<M_, 256>>>(hidden, anw, xnorm, H_);

    // 2) fused QKV projection
    gemm_tf32<<<dim3(QKV_N_ / 256, M_ / 128), 256, GEMM_SMEM_BYTES>>>(xnorm, Wqkv, nullptr, qkv, M_, QKV_N_, H_);

    // 3) q/k norm + rope (in place)
    qknorm_rope_kernel<<<M_ * NH_, DH_>>>(qkv, QKV_N_, qnw, cosp, sinp, NH_);
    qknorm_rope_kernel<<<M_ * NKV_, DH_>>>(qkv + 2048, QKV_N_, knw, cosp, sinp, NKV_);

    // 4) attention (tensor cores)
    attn_kernel<<<dim3(S_ / 128, NH_, B_), 256, attn_smem>>>(qkv, attn);

    // 5) O projection + residual
    gemm_tf32<<<dim3(H_ / 256, M_ / 128), 256, GEMM_SMEM_BYTES>>>(attn, Wo, hidden, h1, M_, H_, NH_ * DH_);

    // 6) mlp rmsnorm (tf32 out)
    rmsnorm_kernel<<<M_, 256>>>(h1, mnw, x2, H_);

    // 7) fused gate+up projection
    gemm_tf32<<<dim3(GU_N_ / 256, M_ / 128), 256, GEMM_SMEM_BYTES>>>(x2, Wgu, nullptr, gu, M_, GU_N_, H_);

    // 8) silu * up (tf32 out)
    {
        long total4 = (long)M_ * I_ / 4;
        int blocks = (int)((total4 + 255) / 256);
        silu_mul_kernel<<<blocks, 256>>>(gu, act, total4);
    }

    // 9) down projection + residual -> output
    gemm_tf32<<<dim3(H_ / 256, M_ / 128), 256, GEMM_SMEM_BYTES>>>(act, Wdn, h1, out, M_, H_, I_);
}

// round 8
// speedup vs baseline: 3.8366x; 1.6496x over previous
#include <cuda_runtime.h>
#include <cuda_fp16.h>
#include <math.h>
#include <stdint.h>

#define B_   2
#define S_   2048
#define H_   2048
#define NH_  16
#define NKV_ 4
#define DH_  128
#define I_   8192
#define M_   (B_ * S_)          // 4096 tokens
#define GROUPS_ (NH_ / NKV_)    // 4
#define EPS_ 1e-6f

#define QKV_N_ 3072             // 2048 q + 512 k + 512 v
#define GU_N_  16384            // 8192 gate + 8192 up

// ---------------- scratch (device globals; no runtime allocation) ----------------
__device__ __half g_xnorm16[(size_t)M_ * H_];
__device__ float  g_qkv[(size_t)M_ * QKV_N_];
__device__ __half g_attn16[(size_t)M_ * H_];
__device__ float  g_h1[(size_t)M_ * H_];
__device__ __half g_x216[(size_t)M_ * H_];
__device__ float  g_gu[(size_t)M_ * GU_N_];
__device__ __half g_act16[(size_t)M_ * I_];
// fp16 transposed weights: Wt[n][k] row-major
__device__ __half w_qkv[(size_t)QKV_N_ * H_];
__device__ __half w_o[(size_t)H_ * H_];
__device__ __half w_gu[(size_t)GU_N_ * H_];
__device__ __half w_dn[(size_t)H_ * I_];

// ---------------- helpers ----------------
__device__ __forceinline__ uint32_t smem_u32(const void* p) {
    return (uint32_t)__cvta_generic_to_shared(p);
}
__device__ __forceinline__ void cp_async16(uint32_t dst, const void* src) {
    asm volatile("cp.async.cg.shared.global [%0], [%1], 16;\n" :: "r"(dst), "l"(src));
}
__device__ __forceinline__ void cp_commit() { asm volatile("cp.async.commit_group;\n"); }
__device__ __forceinline__ void cp_wait0()  { asm volatile("cp.async.wait_group 0;\n"); }
__device__ __forceinline__ void cp_wait1()  { asm volatile("cp.async.wait_group 1;\n"); }
__device__ __forceinline__ void cp_wait2()  { asm volatile("cp.async.wait_group 2;\n"); }

__device__ __forceinline__ void mma_f16(float* d, const uint32_t* a, uint32_t b0, uint32_t b1) {
    asm volatile(
        "mma.sync.aligned.m16n8k16.row.col.f32.f16.f16.f32 "
        "{%0,%1,%2,%3}, {%4,%5,%6,%7}, {%8,%9}, {%0,%1,%2,%3};\n"
        : "+f"(d[0]), "+f"(d[1]), "+f"(d[2]), "+f"(d[3])
        : "r"(a[0]), "r"(a[1]), "r"(a[2]), "r"(a[3]), "r"(b0), "r"(b1));
}

__device__ __forceinline__ uint32_t packh(float a, float b) {
    __half2 h = __floats2half2_rn(a, b);
    return *(uint32_t*)&h;
}

// ---------------- weight transpose + fp16 convert: W[K][N] -> Wt[rowOff+n][k] ----------------
__global__ void transpose_cvt_h(const float* __restrict__ src, __half* __restrict__ dst,
                                int K, int N, int rowOff) {
    __shared__ float tile[32][33];
    int k0 = blockIdx.y * 32, n0 = blockIdx.x * 32;
    int tx = threadIdx.x, ty = threadIdx.y;   // 32 x 8
    #pragma unroll
    for (int i = 0; i < 32; i += 8)
        tile[ty + i][tx] = src[(long)(k0 + ty + i) * N + n0 + tx];
    __syncthreads();
    #pragma unroll
    for (int i = 0; i < 32; i += 8)
        dst[(long)(rowOff + n0 + ty + i) * K + k0 + tx] = __float2half_rn(tile[tx][ty + i]);
}

// ---------------- RMSNorm: fp32 in, fp16 out ----------------
__global__ void rmsnorm_kernel(const float* __restrict__ x, const float* __restrict__ w,
                               __half* __restrict__ y, int Hdim) {
    int row = blockIdx.x;
    const float4* xr = (const float4*)(x + (size_t)row * Hdim);
    uint2* yr = (uint2*)(y + (size_t)row * Hdim);
    const float4* wv = (const float4*)w;
    int n4 = Hdim >> 2;

    float ss = 0.f;
    for (int i = threadIdx.x; i < n4; i += blockDim.x) {
        float4 v = xr[i];
        ss += v.x * v.x + v.y * v.y + v.z * v.z + v.w * v.w;
    }
    __shared__ float wsum[8];
    for (int o = 16; o > 0; o >>= 1) ss += __shfl_xor_sync(0xffffffffu, ss, o);
    int warp = threadIdx.x >> 5;
    if ((threadIdx.x & 31) == 0) wsum[warp] = ss;
    __syncthreads();
    __shared__ float s_inv;
    if (threadIdx.x == 0) {
        float t = 0.f;
        #pragma unroll
        for (int i = 0; i < 8; i++) t += wsum[i];
        s_inv = rsqrtf(t / (float)Hdim + EPS_);
    }
    __syncthreads();
    float inv = s_inv;
    for (int i = threadIdx.x; i < n4; i += blockDim.x) {
        float4 v = xr[i];
        float4 ww = wv[i];
        uint2 o;
        o.x = packh(v.x * inv * ww.x, v.y * inv * ww.y);
        o.y = packh(v.z * inv * ww.z, v.w * inv * ww.w);
        yr[i] = o;
    }
}

// ---------------- per-(token,head) RMSNorm + RoPE (fp32 in place) ----------------
__global__ void qknorm_rope_kernel(float* __restrict__ base, int rowStride,
                                   const float* __restrict__ w,
                                   const float* __restrict__ cosp, const float* __restrict__ sinp,
                                   int nheads) {
    int idx = blockIdx.x;
    int head = idx % nheads;
    int token = idx / nheads;
    float* p = base + (size_t)token * rowStride + head * DH_;
    int d = threadIdx.x;

    float v = p[d];
    float ss = v * v;
    for (int o = 16; o > 0; o >>= 1) ss += __shfl_xor_sync(0xffffffffu, ss, o);
    __shared__ float wsum[4];
    int warp = d >> 5;
    if ((d & 31) == 0) wsum[warp] = ss;
    __syncthreads();
    float tot = wsum[0] + wsum[1] + wsum[2] + wsum[3];
    float inv = rsqrtf(tot / (float)DH_ + EPS_);
    float vn = v * inv * w[d];

    __shared__ float sh[DH_];
    sh[d] = vn;
    __syncthreads();
    float other = (d < 64) ? -sh[d + 64] : sh[d - 64];
    float c = cosp[(size_t)token * DH_ + d];
    float s = sinp[(size_t)token * DH_ + d];
    p[d] = vn * c + other * s;
}

// ---------------- fp16 tensor-core GEMM ----------------
// C[M,N] = A[M,K] @ Wt[N,K]^T (+Res). A fp16 [M][K], Wt fp16 [N][K].
// 128x256x32 block tile, 8 warps (2x4), warp tile 64x64, m16n8k16, 4-stage cp.async.
#define GPA 40    // halves per A smem row (32 k + 8 pad)
#define GPB 40    // halves per B smem row
#define G_ASZ (128 * GPA)                    // halves
#define G_BSZ (256 * GPB)
#define G_STAGE (G_ASZ + G_BSZ)              // 15360 halves = 30720 B
#define G_NSTAGE 4
#define GEMM_SMEM_BYTES (G_NSTAGE * G_STAGE * 2)

__device__ __forceinline__ void gemm_issue(const __half* __restrict__ A, long K, long rowBase,
                                           const __half* __restrict__ Bt, long colBase,
                                           __half* As, __half* Bs, int tid, int k0) {
    // A: 128 rows x 32 halves (64B) -> 4 cp16/row; thread t: row t/2, half-row t%2
    {
        int r = tid >> 1, hf = tid & 1;
        uint32_t dst = smem_u32(As + r * GPA + hf * 16);
        const __half* src = A + (rowBase + r) * K + k0 + hf * 16;
        cp_async16(dst, src);
        cp_async16(dst + 16, src + 8);
    }
    // B: 256 rows x 4 cp16 = 1024; thread t chunk p: f = t + p*256: n=f>>2, kc=f&3
    #pragma unroll
    for (int p = 0; p < 4; p++) {
        int f = tid + p * 256;
        int n = f >> 2, kc = f & 3;
        cp_async16(smem_u32(Bs + n * GPB + kc * 8),
                   Bt + (colBase + n) * K + k0 + kc * 8);
    }
}

__device__ __forceinline__ void gemm_compute(const __half* As, const __half* Bs,
                                             int wm, int wn, int gid, int tig,
                                             float (&acc)[4][8][4]) {
    #pragma unroll
    for (int kk = 0; kk < 32; kk += 16) {
        uint32_t a[4][4];
        #pragma unroll
        for (int mi = 0; mi < 4; mi++) {
            const __half* ap = As + (wm + mi * 16 + gid) * GPA + kk + tig * 2;
            a[mi][0] = *(const uint32_t*)(ap);
            a[mi][1] = *(const uint32_t*)(ap + 8 * GPA);
            a[mi][2] = *(const uint32_t*)(ap + 8);
            a[mi][3] = *(const uint32_t*)(ap + 8 * GPA + 8);
        }
        #pragma unroll
        for (int ni = 0; ni < 8; ni++) {
            const __half* bp = Bs + (wn + ni * 8 + gid) * GPB + kk + tig * 2;
            uint32_t b0 = *(const uint32_t*)(bp);
            uint32_t b1 = *(const uint32_t*)(bp + 8);
            #pragma unroll
            for (int mi = 0; mi < 4; mi++)
                mma_f16(acc[mi][ni], a[mi], b0, b1);
        }
    }
}

__global__ __launch_bounds__(256, 1) void gemm_f16(const __half* __restrict__ A,
                                                   const __half* __restrict__ Bt,
                                                   const float* __restrict__ Res,
                                                   float* __restrict__ C,
                                                   int N, int K) {
    extern __shared__ __half smh[];
    int tid = threadIdx.x;
    int wid = tid >> 5, lane = tid & 31;
    int gid = lane >> 2, tig = lane & 3;
    int wm = (wid >> 2) * 64, wn = (wid & 3) * 64;
    long rowBase = (long)blockIdx.y * 128;
    long colBase = (long)blockIdx.x * 256;

    float acc[4][8][4] = {};

    __half* As[G_NSTAGE];
    __half* Bs[G_NSTAGE];
    #pragma unroll
    for (int s = 0; s < G_NSTAGE; s++) {
        As[s] = smh + s * G_STAGE;
        Bs[s] = As[s] + G_ASZ;
    }

    int nIter = K / 32;
    #pragma unroll
    for (int s = 0; s < 3; s++) {
        gemm_issue(A, K, rowBase, Bt, colBase, As[s], Bs[s], tid, s * 32);
        cp_commit();
    }

    for (int it = 0; it < nIter; it++) {
        if (it + 2 < nIter) cp_wait2();
        else if (it + 1 < nIter) cp_wait1();
        else cp_wait0();
        __syncthreads();

        if (it + 3 < nIter) {
            gemm_issue(A, K, rowBase, Bt, colBase,
                       As[(it + 3) & 3], Bs[(it + 3) & 3], tid, (it + 3) * 32);
            cp_commit();
        }
        gemm_compute(As[it & 3], Bs[it & 3], wm, wn, gid, tig, acc);
    }

    #pragma unroll
    for (int mi = 0; mi < 4; mi++) {
        #pragma unroll
        for (int ni = 0; ni < 8; ni++) {
            long r0 = rowBase + wm + mi * 16 + gid;
            long c = colBase + wn + ni * 8 + tig * 2;
            float2 v0 = make_float2(acc[mi][ni][0], acc[mi][ni][1]);
            float2 v1 = make_float2(acc[mi][ni][2], acc[mi][ni][3]);
            if (Res != nullptr) {
                float2 r0v = *(const float2*)(Res + r0 * N + c);
                float2 r1v = *(const float2*)(Res + (r0 + 8) * N + c);
                v0.x += r0v.x; v0.y += r0v.y;
                v1.x += r1v.x; v1.y += r1v.y;
            }
            *(float2*)(C + r0 * N + c) = v0;
            *(float2*)(C + (r0 + 8) * N + c) = v1;
        }
    }
}

// ---------------- fp16 tensor-core flash attention ----------------
// Block: 128 q-rows x full DH. 256 thr = 8 warps, warp = 16 q-rows. kv tiles of 64.
// smem: Ks[64][136]h, Vs[64][136]h; Q prologue aliases both (128x136h).
#define KST 136
#define AT_SMEM_BYTES (2 * 64 * KST * 2)   // 34816

__global__ __launch_bounds__(256, 1) void attn_kernel(const float* __restrict__ qkv,
                                                      __half* __restrict__ o) {
    extern __shared__ __half smh[];
    __half* Ks = smh;                 // 64 x 136
    __half* Vs = smh + 64 * KST;      // 64 x 136
    __half* Qs = smh;                 // 128 x 136 (prologue alias)

    int qb = blockIdx.x, h = blockIdx.y, b = blockIdx.z;
    int kvh = h / GROUPS_;
    int tid = threadIdx.x;
    int w = tid >> 5, lane = tid & 31;
    int gid = lane >> 2, tig = lane & 3;
    int wq = w * 16;
    long bS = (long)b * S_;

    const float scale = 0.08838834764831845f;  // 1/sqrt(128)

    // prologue: Q -> fp16 smem, then per-warp A-frags into regs
    for (int i = tid; i < 128 * 32; i += 256) {
        int r = i >> 5, c4 = (i & 31) * 4;
        float4 v = *(const float4*)(qkv + (bS + qb * 128 + r) * QKV_N_ + h * DH_ + c4);
        uint2 pk;
        pk.x = packh(v.x * scale, v.y * scale);
        pk.y = packh(v.z * scale, v.w * scale);
        *(uint2*)(Qs + r * KST + c4) = pk;
    }
    __syncthreads();
    uint32_t qf[8][4];
    #pragma unroll
    for (int kk = 0; kk < 8; kk++) {
        const __half* qp = Qs + (wq + gid) * KST + kk * 16 + tig * 2;
        qf[kk][0] = *(const uint32_t*)(qp);
        qf[kk][1] = *(const uint32_t*)(qp + 8 * KST);
        qf[kk][2] = *(const uint32_t*)(qp + 8);
        qf[kk][3] = *(const uint32_t*)(qp + 8 * KST + 8);
    }
    __syncthreads();

    float of[16][4] = {};
    float m0 = -INFINITY, m1 = -INFINITY, l0 = 0.f, l1 = 0.f;

    // ldmatrix V address components
    int lrow = lane & 15;        // row within 16-j chunk
    int lsel = lane >> 4;        // 0/1 -> d-offset 0/8

    for (int kt = 0; kt < S_ / 64; kt++) {
        // fill K,V (fp32 -> fp16)
        for (int i = tid; i < 64 * 32; i += 256) {
            int r = i >> 5, c4 = (i & 31) * 4;
            long gb = (bS + kt * 64 + r) * QKV_N_ + kvh * DH_ + c4;
            float4 kv = *(const float4*)(qkv + 2048 + gb);
            uint2 pk;
            pk.x = packh(kv.x, kv.y); pk.y = packh(kv.z, kv.w);
            *(uint2*)(Ks + r * KST + c4) = pk;
            float4 vv = *(const float4*)(qkv + 2560 + gb);
            pk.x = packh(vv.x, vv.y); pk.y = packh(vv.z, vv.w);
            *(uint2*)(Vs + r * KST + c4) = pk;
        }
        __syncthreads();

        // scores: S[16 x 64] per warp
        float sc[8][4] = {};
        #pragma unroll
        for (int kk = 0; kk < 8; kk++) {
            #pragma unroll
            for (int ni = 0; ni < 8; ni++) {
                const __half* kp = Ks + (ni * 8 + gid) * KST + kk * 16 + tig * 2;
                uint32_t b0 = *(const uint32_t*)(kp);
                uint32_t b1 = *(const uint32_t*)(kp + 8);
                mma_f16(sc[ni], qf[kk], b0, b1);
            }
        }

        // online softmax (rows gid, gid+8)
        float mx0 = -INFINITY, mx1 = -INFINITY;
        #pragma unroll
        for (int ni = 0; ni < 8; ni++) {
            mx0 = fmaxf(mx0, fmaxf(sc[ni][0], sc[ni][1]));
            mx1 = fmaxf(mx1, fmaxf(sc[ni][2], sc[ni][3]));
        }
        mx0 = fmaxf(mx0, __shfl_xor_sync(0xffffffffu, mx0, 1));
        mx0 = fmaxf(mx0, __shfl_xor_sync(0xffffffffu, mx0, 2));
        mx1 = fmaxf(mx1, __shfl_xor_sync(0xffffffffu, mx1, 1));
        mx1 = fmaxf(mx1, __shfl_xor_sync(0xffffffffu, mx1, 2));
        float nm0 = fmaxf(m0, mx0), nm1 = fmaxf(m1, mx1);
        float s0 = 0.f, s1 = 0.f;
        #pragma unroll
        for (int ni = 0; ni < 8; ni++) {
            // round-trip through fp16 so the P used by mma matches the l sum
            float e0 = __half2float(__float2half_rn(__expf(sc[ni][0] - nm0)));
            float e1 = __half2float(__float2half_rn(__expf(sc[ni][1] - nm0)));
            float e2 = __half2float(__float2half_rn(__expf(sc[ni][2] - nm1)));
            float e3 = __half2float(__float2half_rn(__expf(sc[ni][3] - nm1)));
            sc[ni][0] = e0; sc[ni][1] = e1; sc[ni][2] = e2; sc[ni][3] = e3;
            s0 += e0 + e1; s1 += e2 + e3;
        }
        s0 += __shfl_xor_sync(0xffffffffu, s0, 1);
        s0 += __shfl_xor_sync(0xffffffffu, s0, 2);
        s1 += __shfl_xor_sync(0xffffffffu, s1, 1);
        s1 += __shfl_xor_sync(0xffffffffu, s1, 2);
        float a0 = __expf(m0 - nm0), a1 = __expf(m1 - nm1);
        l0 = l0 * a0 + s0; l1 = l1 * a1 + s1;
        m0 = nm0; m1 = nm1;
        #pragma unroll
        for (int ni = 0; ni < 16; ni++) {
            of[ni][0] *= a0; of[ni][1] *= a0;
            of[ni][2] *= a1; of[ni][3] *= a1;
        }

        // O += P @ V : P repacked from score C-frags, V via ldmatrix.x4.trans
        #pragma unroll
        for (int t = 0; t < 4; t++) {   // j chunks of 16
            uint32_t pa[4];
            pa[0] = packh(sc[2 * t][0], sc[2 * t][1]);
            pa[1] = packh(sc[2 * t][2], sc[2 * t][3]);
            pa[2] = packh(sc[2 * t + 1][0], sc[2 * t + 1][1]);
            pa[3] = packh(sc[2 * t + 1][2], sc[2 * t + 1][3]);
            uint32_t vbase = smem_u32(Vs + (t * 16 + lrow) * KST + lsel * 8);
            #pragma unroll
            for (int ni2 = 0; ni2 < 8; ni2++) {   // d chunks of 16
                uint32_t r0, r1, r2, r3;
                asm volatile(
                    "ldmatrix.sync.aligned.m8n8.x4.trans.shared.b16 {%0,%1,%2,%3}, [%4];"
                    : "=r"(r0), "=r"(r1), "=r"(r2), "=r"(r3)
                    : "r"(vbase + ni2 * 32u));   // 16 halves = 32 bytes
                mma_f16(of[2 * ni2], pa, r0, r1);
                mma_f16(of[2 * ni2 + 1], pa, r2, r3);
            }
        }
        __syncthreads();
    }

    // epilogue: normalize, write fp16 (b,s,h,d)
    float inv0 = 1.f / l0, inv1 = 1.f / l1;
    long r0 = bS + qb * 128 + wq + gid;
    long r1 = r0 + 8;
    #pragma unroll
    for (int nt = 0; nt < 16; nt++) {
        int d = nt * 8 + tig * 2;
        *(uint32_t*)(o + (r0 * NH_ + h) * DH_ + d) = packh(of[nt][0] * inv0, of[nt][1] * inv0);
        *(uint32_t*)(o + (r1 * NH_ + h) * DH_ + d) = packh(of[nt][2] * inv1, of[nt][3] * inv1);
    }
}

// ---------------- silu(gate) * up -> fp16 ----------------
__global__ void silu_mul_kernel(const float* __restrict__ gu, __half* __restrict__ out, long total4) {
    long i = (long)blockIdx.x * blockDim.x + threadIdx.x;
    if (i >= total4) return;
    long mrow = i >> 11;             // 2048 float4-chunks per row of I_
    int c4 = (int)(i & 2047);
    const float4* gu4 = (const float4*)gu;
    float4 gv = gu4[mrow * 4096 + c4];
    float4 uv = gu4[mrow * 4096 + 2048 + c4];
    uint2 o;
    o.x = packh(gv.x / (1.f + __expf(-gv.x)) * uv.x,
                gv.y / (1.f + __expf(-gv.y)) * uv.y);
    o.y = packh(gv.z / (1.f + __expf(-gv.z)) * uv.z,
                gv.w / (1.f + __expf(-gv.w)) * uv.w);
    *(uint2*)(out + mrow * I_ + c4 * 4) = o;
}

// ---------------- launch ----------------
extern "C" void kernel_launch(void* const* d_in, const int* in_sizes, int n_in,
                              void* d_out, int out_size) {
    const float* hidden = (const float*)d_in[0];
    const float* cosp   = (const float*)d_in[1];
    const float* sinp   = (const float*)d_in[2];
    const float* wq     = (const float*)d_in[3];
    const float* wk     = (const float*)d_in[4];
    const float* wv     = (const float*)d_in[5];
    const float* wo     = (const float*)d_in[6];
    const float* qnw    = (const float*)d_in[7];
    const float* knw    = (const float*)d_in[8];
    const float* anw    = (const float*)d_in[9];
    const float* mnw    = (const float*)d_in[10];
    const float* wgate  = (const float*)d_in[11];
    const float* wup    = (const float*)d_in[12];
    const float* wdown  = (const float*)d_in[13];
    float* out = (float*)d_out;

    __half *xnorm, *attn, *x2, *act, *Wqkv, *Wo, *Wgu, *Wdn;
    float *qkv, *h1, *gu;
    cudaGetSymbolAddress((void**)&xnorm, g_xnorm16);
    cudaGetSymbolAddress((void**)&qkv, g_qkv);
    cudaGetSymbolAddress((void**)&attn, g_attn16);
    cudaGetSymbolAddress((void**)&h1, g_h1);
    cudaGetSymbolAddress((void**)&x2, g_x216);
    cudaGetSymbolAddress((void**)&gu, g_gu);
    cudaGetSymbolAddress((void**)&act, g_act16);
    cudaGetSymbolAddress((void**)&Wqkv, w_qkv);
    cudaGetSymbolAddress((void**)&Wo, w_o);
    cudaGetSymbolAddress((void**)&Wgu, w_gu);
    cudaGetSymbolAddress((void**)&Wdn, w_dn);

    cudaFuncSetAttribute(attn_kernel, cudaFuncAttributeMaxDynamicSharedMemorySize, AT_SMEM_BYTES);
    cudaFuncSetAttribute(gemm_f16, cudaFuncAttributeMaxDynamicSharedMemorySize, GEMM_SMEM_BYTES);

    // 0) transpose + fp16-convert weights -> Wt[n][k]
    dim3 tb(32, 8);
    transpose_cvt_h<<<dim3(H_ / 32, H_ / 32), tb>>>(wq, Wqkv, H_, H_, 0);
    transpose_cvt_h<<<dim3(512 / 32, H_ / 32), tb>>>(wk, Wqkv, H_, 512, 2048);
    transpose_cvt_h<<<dim3(512 / 32, H_ / 32), tb>>>(wv, Wqkv, H_, 512, 2560);
    transpose_cvt_h<<<dim3(H_ / 32, H_ / 32), tb>>>(wo, Wo, H_, H_, 0);
    transpose_cvt_h<<<dim3(I_ / 32, H_ / 32), tb>>>(wgate, Wgu, H_, I_, 0);
    transpose_cvt_h<<<dim3(I_ / 32, H_ / 32), tb>>>(wup, Wgu, H_, I_, 8192);
    transpose_cvt_h<<<dim3(H_ / 32, I_ / 32), tb>>>(wdown, Wdn, I_, H_, 0);

    // 1) attn rmsnorm (fp16 out)
    rmsnorm_kernel<<<M_, 256>>>(hidden, anw, xnorm, H_);

    // 2) fused QKV projection (fp32 out)
    gemm_f16<<<dim3(QKV_N_ / 256, M_ / 128), 256, GEMM_SMEM_BYTES>>>(xnorm, Wqkv, nullptr, qkv, QKV_N_, H_);

    // 3) q/k norm + rope (fp32 in place)
    qknorm_rope_kernel<<<M_ * NH_, DH_>>>(qkv, QKV_N_, qnw, cosp, sinp, NH_);
    qknorm_rope_kernel<<<M_ * NKV_, DH_>>>(qkv + 2048, QKV_N_, knw, cosp, sinp, NKV_);

    // 4) attention (fp16 mma, fp16 out)
    attn_kernel<<<dim3(S_ / 128, NH_, B_), 256, AT_SMEM_BYTES>>>(qkv, attn);

    // 5) O projection + residual (fp32 out)
    gemm_f16<<<dim3(H_ / 256, M_ / 128), 256, GEMM_SMEM_BYTES>>>(attn, Wo, hidden, h1, H_, H_);

    // 6) mlp rmsnorm (fp16 out)
    rmsnorm_kernel<<<M_, 256>>>(h1, mnw, x2, H_);

    // 7) fused gate+up projection (fp32 out)
    gemm_f16<<<dim3(GU_N_ / 256, M_ / 128), 256, GEMM_SMEM_BYTES>>>(x2, Wgu, nullptr, gu, GU_N_, H_);

    // 8) silu * up (fp16 out)
    {
        long total4 = (long)M_ * I_ / 4;
        int blocks = (int)((total4 + 255) / 256);
        silu_mul_kernel<<<blocks, 256>>>(gu, act, total4);
    }

    // 9) down projection + residual -> output (fp32)
    gemm_f16<<<dim3(H_ / 256, M_ / 128), 256, GEMM_SMEM_BYTES>>>(act, Wdn, h1, out, H_, I_);
}

// round 9
// speedup vs baseline: 3.9781x; 1.0369x over previous
#include <cuda_runtime.h>
#include <cuda_fp16.h>
#include <math.h>
#include <stdint.h>

#define B_   2
#define S_   2048
#define H_   2048
#define NH_  16
#define NKV_ 4
#define DH_  128
#define I_   8192
#define M_   (B_ * S_)          // 4096 tokens
#define GROUPS_ (NH_ / NKV_)    // 4
#define EPS_ 1e-6f

#define QKV_N_ 3072             // 2048 q + 512 k + 512 v
#define GU_N_  16384            // 8192 gate + 8192 up (INTERLEAVED: col 2j=gate_j, 2j+1=up_j)

// ---------------- scratch (device globals; no runtime allocation) ----------------
__device__ __half g_xnorm16[(size_t)M_ * H_];
__device__ float  g_qkv[(size_t)M_ * QKV_N_];
__device__ __half g_q16[(size_t)B_ * NH_ * S_ * DH_];    // (b,h,s,d), pre-scaled
__device__ __half g_k16[(size_t)B_ * NKV_ * S_ * DH_];   // (b,kvh,s,d)
__device__ __half g_v16[(size_t)B_ * NKV_ * S_ * DH_];   // (b,kvh,s,d)
__device__ __half g_attn16[(size_t)M_ * H_];
__device__ float  g_h1[(size_t)M_ * H_];
__device__ __half g_x216[(size_t)M_ * H_];
__device__ __half g_act16[(size_t)M_ * I_];
// fp16 transposed weights: Wt[n][k] row-major
__device__ __half w_qkv[(size_t)QKV_N_ * H_];
__device__ __half w_o[(size_t)H_ * H_];
__device__ __half w_gu[(size_t)GU_N_ * H_];
__device__ __half w_dn[(size_t)H_ * I_];

// ---------------- helpers ----------------
__device__ __forceinline__ uint32_t smem_u32(const void* p) {
    return (uint32_t)__cvta_generic_to_shared(p);
}
__device__ __forceinline__ void cp_async16(uint32_t dst, const void* src) {
    asm volatile("cp.async.cg.shared.global [%0], [%1], 16;\n" :: "r"(dst), "l"(src));
}
__device__ __forceinline__ void cp_commit() { asm volatile("cp.async.commit_group;\n"); }
__device__ __forceinline__ void cp_wait0()  { asm volatile("cp.async.wait_group 0;\n"); }
__device__ __forceinline__ void cp_wait1()  { asm volatile("cp.async.wait_group 1;\n"); }
__device__ __forceinline__ void cp_wait2()  { asm volatile("cp.async.wait_group 2;\n"); }

__device__ __forceinline__ void mma_f16(float* d, const uint32_t* a, uint32_t b0, uint32_t b1) {
    asm volatile(
        "mma.sync.aligned.m16n8k16.row.col.f32.f16.f16.f32 "
        "{%0,%1,%2,%3}, {%4,%5,%6,%7}, {%8,%9}, {%0,%1,%2,%3};\n"
        : "+f"(d[0]), "+f"(d[1]), "+f"(d[2]), "+f"(d[3])
        : "r"(a[0]), "r"(a[1]), "r"(a[2]), "r"(a[3]), "r"(b0), "r"(b1));
}

__device__ __forceinline__ uint32_t packh(float a, float b) {
    __half2 h = __floats2half2_rn(a, b);
    return *(uint32_t*)&h;
}

// ---------------- fast transpose + fp16 convert ----------------
// src: W[K][N] fp32. dst row (rowOff + n*rmul) of length K fp16.
// 64x64 tiles, 256 threads: coalesced float4 reads, coalesced 16B fp16 writes.
__global__ void transpose_cvt_h(const float* __restrict__ src, __half* __restrict__ dst,
                                int K, int N, int rowOff, int rmul) {
    __shared__ float tile[64][65];
    long k0 = (long)blockIdx.y * 64, n0 = (long)blockIdx.x * 64;
    int t = threadIdx.x;
    {
        int r = t >> 2, c = (t & 3) * 16;
        const float* s = src + (k0 + r) * N + n0 + c;
        #pragma unroll
        for (int i = 0; i < 4; i++) {
            float4 v = *(const float4*)(s + i * 4);
            tile[r][c + i * 4 + 0] = v.x; tile[r][c + i * 4 + 1] = v.y;
            tile[r][c + i * 4 + 2] = v.z; tile[r][c + i * 4 + 3] = v.w;
        }
    }
    __syncthreads();
    #pragma unroll
    for (int wv = 0; wv < 2; wv++) {
        int n = (t >> 3) + wv * 32;
        int ks = (t & 7) * 8;
        uint2 lo, hi;
        lo.x = packh(tile[ks + 0][n], tile[ks + 1][n]);
        lo.y = packh(tile[ks + 2][n], tile[ks + 3][n]);
        hi.x = packh(tile[ks + 4][n], tile[ks + 5][n]);
        hi.y = packh(tile[ks + 6][n], tile[ks + 7][n]);
        uint4 o = make_uint4(lo.x, lo.y, hi.x, hi.y);
        *(uint4*)(dst + (long)(rowOff + (n0 + n) * rmul) * K + k0 + ks) = o;
    }
}

// ---------------- RMSNorm: fp32 in, fp16 out ----------------
__global__ void rmsnorm_kernel(const float* __restrict__ x, const float* __restrict__ w,
                               __half* __restrict__ y, int Hdim) {
    int row = blockIdx.x;
    const float4* xr = (const float4*)(x + (size_t)row * Hdim);
    uint2* yr = (uint2*)(y + (size_t)row * Hdim);
    const float4* wv = (const float4*)w;
    int n4 = Hdim >> 2;

    float ss = 0.f;
    for (int i = threadIdx.x; i < n4; i += blockDim.x) {
        float4 v = xr[i];
        ss += v.x * v.x + v.y * v.y + v.z * v.z + v.w * v.w;
    }
    __shared__ float wsum[8];
    for (int o = 16; o > 0; o >>= 1) ss += __shfl_xor_sync(0xffffffffu, ss, o);
    int warp = threadIdx.x >> 5;
    if ((threadIdx.x & 31) == 0) wsum[warp] = ss;
    __syncthreads();
    __shared__ float s_inv;
    if (threadIdx.x == 0) {
        float t = 0.f;
        #pragma unroll
        for (int i = 0; i < 8; i++) t += wsum[i];
        s_inv = rsqrtf(t / (float)Hdim + EPS_);
    }
    __syncthreads();
    float inv = s_inv;
    for (int i = threadIdx.x; i < n4; i += blockDim.x) {
        float4 v = xr[i];
        float4 ww = wv[i];
        uint2 o;
        o.x = packh(v.x * inv * ww.x, v.y * inv * ww.y);
        o.y = packh(v.z * inv * ww.z, v.w * inv * ww.w);
        yr[i] = o;
    }
}

// ---------------- per-(token,head) RMSNorm + RoPE -> fp16 (b,head,s,d) ----------------
__global__ void qknorm_rope_kernel(const float* __restrict__ qkvbase, int colOff,
                                   const float* __restrict__ w,
                                   const float* __restrict__ cosp, const float* __restrict__ sinp,
                                   int nheads, __half* __restrict__ dst, float outScale) {
    int idx = blockIdx.x;
    int head = idx % nheads;
    int token = idx / nheads;
    const float* p = qkvbase + (size_t)token * QKV_N_ + colOff + head * DH_;
    int d = threadIdx.x;

    float v = p[d];
    float ss = v * v;
    for (int o = 16; o > 0; o >>= 1) ss += __shfl_xor_sync(0xffffffffu, ss, o);
    __shared__ float wsum[4];
    int warp = d >> 5;
    if ((d & 31) == 0) wsum[warp] = ss;
    __syncthreads();
    float tot = wsum[0] + wsum[1] + wsum[2] + wsum[3];
    float inv = rsqrtf(tot / (float)DH_ + EPS_);
    float vn = v * inv * w[d];

    __shared__ float sh[DH_];
    sh[d] = vn;
    __syncthreads();
    float other = (d < 64) ? -sh[d + 64] : sh[d - 64];
    float c = cosp[(size_t)token * DH_ + d];
    float s = sinp[(size_t)token * DH_ + d];
    float r = (vn * c + other * s) * outScale;

    int b = token >> 11, sq = token & 2047;     // S_ = 2048
    dst[(((size_t)b * nheads + head) * S_ + sq) * DH_ + d] = __float2half_rn(r);
}

// ---------------- v convert: qkv fp32 -> v16 (b,kvh,s,d) fp16 ----------------
__global__ void vcvt_kernel(const float* __restrict__ qkv, __half* __restrict__ v16) {
    long i = (long)blockIdx.x * blockDim.x + threadIdx.x;   // over M_*512/4 float4s
    if (i >= (long)M_ * 512 / 4) return;
    int token = (int)(i >> 7);
    int j4 = (int)(i & 127) * 4;            // j within 512
    float4 v = *(const float4*)(qkv + (size_t)token * QKV_N_ + 2560 + j4);
    int kvh = j4 >> 7, d = j4 & 127;
    int b = token >> 11, sq = token & 2047;
    uint2 o;
    o.x = packh(v.x, v.y);
    o.y = packh(v.z, v.w);
    *(uint2*)(v16 + (((size_t)b * NKV_ + kvh) * S_ + sq) * DH_ + d) = o;
}

// ---------------- fp16 tensor-core GEMM ----------------
// C[M,N] = A[M,K] @ Wt[N,K]^T. A fp16 [M][K], Wt fp16 [N][K].
// 128x256x32 block tile, 8 warps (2x4), warp tile 64x64, m16n8k16, 4-stage cp.async.
// mode 0: fp32 C (+ optional Res). mode 1: interleaved silu: act16[r][c/2] = silu(g)*u.
#define GPA 40
#define GPB 40
#define G_ASZ (128 * GPA)
#define G_BSZ (256 * GPB)
#define G_STAGE (G_ASZ + G_BSZ)
#define G_NSTAGE 4
#define GEMM_SMEM_BYTES (G_NSTAGE * G_STAGE * 2)

__device__ __forceinline__ void gemm_issue(const __half* __restrict__ A, long K, long rowBase,
                                           const __half* __restrict__ Bt, long colBase,
                                           __half* As, __half* Bs, int tid, int k0) {
    {
        int r = tid >> 1, hf = tid & 1;
        uint32_t dst = smem_u32(As + r * GPA + hf * 16);
        const __half* src = A + (rowBase + r) * K + k0 + hf * 16;
        cp_async16(dst, src);
        cp_async16(dst + 16, src + 8);
    }
    #pragma unroll
    for (int p = 0; p < 4; p++) {
        int f = tid + p * 256;
        int n = f >> 2, kc = f & 3;
        cp_async16(smem_u32(Bs + n * GPB + kc * 8),
                   Bt + (colBase + n) * K + k0 + kc * 8);
    }
}

__device__ __forceinline__ void gemm_compute(const __half* As, const __half* Bs,
                                             int wm, int wn, int gid, int tig,
                                             float (&acc)[4][8][4]) {
    #pragma unroll
    for (int kk = 0; kk < 32; kk += 16) {
        uint32_t a[4][4];
        #pragma unroll
        for (int mi = 0; mi < 4; mi++) {
            const __half* ap = As + (wm + mi * 16 + gid) * GPA + kk + tig * 2;
            a[mi][0] = *(const uint32_t*)(ap);
            a[mi][1] = *(const uint32_t*)(ap + 8 * GPA);
            a[mi][2] = *(const uint32_t*)(ap + 8);
            a[mi][3] = *(const uint32_t*)(ap + 8 * GPA + 8);
        }
        #pragma unroll
        for (int ni = 0; ni < 8; ni++) {
            const __half* bp = Bs + (wn + ni * 8 + gid) * GPB + kk + tig * 2;
            uint32_t b0 = *(const uint32_t*)(bp);
            uint32_t b1 = *(const uint32_t*)(bp + 8);
            #pragma unroll
            for (int mi = 0; mi < 4; mi++)
                mma_f16(acc[mi][ni], a[mi], b0, b1);
        }
    }
}

__device__ __forceinline__ float silu_mul(float g, float u) {
    return g / (1.f + __expf(-g)) * u;
}

__global__ __launch_bounds__(256, 1) void gemm_f16(const __half* __restrict__ A,
                                                   const __half* __restrict__ Bt,
                                                   const float* __restrict__ Res,
                                                   float* __restrict__ C,
                                                   __half* __restrict__ C16,
                                                   int N, int K, int mode) {
    extern __shared__ __half smh[];
    int tid = threadIdx.x;
    int wid = tid >> 5, lane = tid & 31;
    int gid = lane >> 2, tig = lane & 3;
    int wm = (wid >> 2) * 64, wn = (wid & 3) * 64;
    long rowBase = (long)blockIdx.y * 128;
    long colBase = (long)blockIdx.x * 256;

    float acc[4][8][4] = {};

    __half* As[G_NSTAGE];
    __half* Bs[G_NSTAGE];
    #pragma unroll
    for (int s = 0; s < G_NSTAGE; s++) {
        As[s] = smh + s * G_STAGE;
        Bs[s] = As[s] + G_ASZ;
    }

    int nIter = K / 32;
    #pragma unroll
    for (int s = 0; s < 3; s++) {
        gemm_issue(A, K, rowBase, Bt, colBase, As[s], Bs[s], tid, s * 32);
        cp_commit();
    }

    for (int it = 0; it < nIter; it++) {
        if (it + 2 < nIter) cp_wait2();
        else if (it + 1 < nIter) cp_wait1();
        else cp_wait0();
        __syncthreads();

        if (it + 3 < nIter) {
            gemm_issue(A, K, rowBase, Bt, colBase,
                       As[(it + 3) & 3], Bs[(it + 3) & 3], tid, (it + 3) * 32);
            cp_commit();
        }
        gemm_compute(As[it & 3], Bs[it & 3], wm, wn, gid, tig, acc);
    }

    if (mode == 0) {
        #pragma unroll
        for (int mi = 0; mi < 4; mi++) {
            #pragma unroll
            for (int ni = 0; ni < 8; ni++) {
                long r0 = rowBase + wm + mi * 16 + gid;
                long c = colBase + wn + ni * 8 + tig * 2;
                float2 v0 = make_float2(acc[mi][ni][0], acc[mi][ni][1]);
                float2 v1 = make_float2(acc[mi][ni][2], acc[mi][ni][3]);
                if (Res != nullptr) {
                    float2 r0v = *(const float2*)(Res + r0 * N + c);
                    float2 r1v = *(const float2*)(Res + (r0 + 8) * N + c);
                    v0.x += r0v.x; v0.y += r0v.y;
                    v1.x += r1v.x; v1.y += r1v.y;
                }
                *(float2*)(C + r0 * N + c) = v0;
                *(float2*)(C + (r0 + 8) * N + c) = v1;
            }
        }
    } else {
        // interleaved gate/up -> silu -> fp16 act (out width N/2)
        #pragma unroll
        for (int mi = 0; mi < 4; mi++) {
            #pragma unroll
            for (int ni = 0; ni < 8; ni++) {
                long r0 = rowBase + wm + mi * 16 + gid;
                long j = (colBase + wn + ni * 8 + tig * 2) >> 1;
                C16[r0 * (N / 2) + j] = __float2half_rn(silu_mul(acc[mi][ni][0], acc[mi][ni][1]));
                C16[(r0 + 8) * (N / 2) + j] = __float2half_rn(silu_mul(acc[mi][ni][2], acc[mi][ni][3]));
            }
        }
    }
}

// ---------------- fp16 flash attention, cp.async double-buffered K/V ----------------
// Block: 128 q-rows. 256 thr = 8 warps, warp = 16 q-rows. kv tiles of 64.
#define AST 136                              // halves per K/V smem row
#define AT_STAGE (2 * 64 * AST)              // K + V halves per stage
#define AT_SMEM_BYTES (2 * AT_STAGE * 2)     // 69632 B

__global__ __launch_bounds__(256, 1) void attn_kernel(const __half* __restrict__ q16,
                                                      const __half* __restrict__ k16,
                                                      const __half* __restrict__ v16,
                                                      __half* __restrict__ o) {
    extern __shared__ __half smh[];

    int qb = blockIdx.x, h = blockIdx.y, b = blockIdx.z;
    int kvh = h / GROUPS_;
    int tid = threadIdx.x;
    int w = tid >> 5, lane = tid & 31;
    int gid = lane >> 2, tig = lane & 3;
    int wq = w * 16;
    long bS = (long)b * S_;

    const __half* qh = q16 + (((size_t)b * NH_ + h) * S_ + (size_t)qb * 128) * DH_;
    const __half* kh = k16 + (((size_t)b * NKV_ + kvh) * S_) * DH_;
    const __half* vh = v16 + (((size_t)b * NKV_ + kvh) * S_) * DH_;

    // ---- prologue: Q (pre-scaled fp16) -> smem staging, extract frags
    __half* Qs = smh;    // 128 x 136 (overlaps both stages; freed before tile0 issue)
    for (int i = tid; i < 128 * 16; i += 256) {
        int r = i >> 4, c8 = (i & 15) * 8;
        *(uint4*)(Qs + r * AST + c8) = *(const uint4*)(qh + r * DH_ + c8);
    }
    __syncthreads();
    uint32_t qf[8][4];
    #pragma unroll
    for (int kk = 0; kk < 8; kk++) {
        const __half* qp = Qs + (wq + gid) * AST + kk * 16 + tig * 2;
        qf[kk][0] = *(const uint32_t*)(qp);
        qf[kk][1] = *(const uint32_t*)(qp + 8 * AST);
        qf[kk][2] = *(const uint32_t*)(qp + 8);
        qf[kk][3] = *(const uint32_t*)(qp + 8 * AST + 8);
    }
    __syncthreads();

    float of[16][4] = {};
    float m0 = -INFINITY, m1 = -INFINITY, l0 = 0.f, l1 = 0.f;

    int lrow = lane & 15, lsel = lane >> 4;

    // issue tile 0 into stage 0
    {
        __half* Ks = smh;
        __half* Vs = smh + 64 * AST;
        #pragma unroll
        for (int p = 0; p < 4; p++) {
            int f = tid + p * 256;
            int r = f >> 4, c8 = (f & 15) * 8;
            cp_async16(smem_u32(Ks + r * AST + c8), kh + r * DH_ + c8);
            cp_async16(smem_u32(Vs + r * AST + c8), vh + r * DH_ + c8);
        }
        cp_commit();
    }

    const int nTiles = S_ / 64;
    for (int kt = 0; kt < nTiles; kt++) {
        if (kt + 1 < nTiles) {
            __half* Kn = smh + ((kt + 1) & 1) * AT_STAGE;
            __half* Vn = Kn + 64 * AST;
            const __half* kb = kh + (size_t)(kt + 1) * 64 * DH_;
            const __half* vb = vh + (size_t)(kt + 1) * 64 * DH_;
            #pragma unroll
            for (int p = 0; p < 4; p++) {
                int f = tid + p * 256;
                int r = f >> 4, c8 = (f & 15) * 8;
                cp_async16(smem_u32(Kn + r * AST + c8), kb + r * DH_ + c8);
                cp_async16(smem_u32(Vn + r * AST + c8), vb + r * DH_ + c8);
            }
            cp_commit();
            cp_wait1();
        } else {
            cp_wait0();
        }
        __syncthreads();

        const __half* Ks = smh + (kt & 1) * AT_STAGE;
        const __half* Vs = Ks + 64 * AST;

        // scores: S[16 x 64] per warp
        float sc[8][4] = {};
        #pragma unroll
        for (int kk = 0; kk < 8; kk++) {
            #pragma unroll
            for (int ni = 0; ni < 8; ni++) {
                const __half* kp = Ks + (ni * 8 + gid) * AST + kk * 16 + tig * 2;
                uint32_t b0 = *(const uint32_t*)(kp);
                uint32_t b1 = *(const uint32_t*)(kp + 8);
                mma_f16(sc[ni], qf[kk], b0, b1);
            }
        }

        // online softmax (rows gid, gid+8)
        float mx0 = -INFINITY, mx1 = -INFINITY;
        #pragma unroll
        for (int ni = 0; ni < 8; ni++) {
            mx0 = fmaxf(mx0, fmaxf(sc[ni][0], sc[ni][1]));
            mx1 = fmaxf(mx1, fmaxf(sc[ni][2], sc[ni][3]));
        }
        mx0 = fmaxf(mx0, __shfl_xor_sync(0xffffffffu, mx0, 1));
        mx0 = fmaxf(mx0, __shfl_xor_sync(0xffffffffu, mx0, 2));
        mx1 = fmaxf(mx1, __shfl_xor_sync(0xffffffffu, mx1, 1));
        mx1 = fmaxf(mx1, __shfl_xor_sync(0xffffffffu, mx1, 2));
        float nm0 = fmaxf(m0, mx0), nm1 = fmaxf(m1, mx1);
        float s0 = 0.f, s1 = 0.f;
        #pragma unroll
        for (int ni = 0; ni < 8; ni++) {
            float e0 = __half2float(__float2half_rn(__expf(sc[ni][0] - nm0)));
            float e1 = __half2float(__float2half_rn(__expf(sc[ni][1] - nm0)));
            float e2 = __half2float(__float2half_rn(__expf(sc[ni][2] - nm1)));
            float e3 = __half2float(__float2half_rn(__expf(sc[ni][3] - nm1)));
            sc[ni][0] = e0; sc[ni][1] = e1; sc[ni][2] = e2; sc[ni][3] = e3;
            s0 += e0 + e1; s1 += e2 + e3;
        }
        s0 += __shfl_xor_sync(0xffffffffu, s0, 1);
        s0 += __shfl_xor_sync(0xffffffffu, s0, 2);
        s1 += __shfl_xor_sync(0xffffffffu, s1, 1);
        s1 += __shfl_xor_sync(0xffffffffu, s1, 2);
        float a0 = __expf(m0 - nm0), a1 = __expf(m1 - nm1);
        l0 = l0 * a0 + s0; l1 = l1 * a1 + s1;
        m0 = nm0; m1 = nm1;
        #pragma unroll
        for (int ni = 0; ni < 16; ni++) {
            of[ni][0] *= a0; of[ni][1] *= a0;
            of[ni][2] *= a1; of[ni][3] *= a1;
        }

        // O += P @ V
        #pragma unroll
        for (int t = 0; t < 4; t++) {
            uint32_t pa[4];
            pa[0] = packh(sc[2 * t][0], sc[2 * t][1]);
            pa[1] = packh(sc[2 * t][2], sc[2 * t][3]);
            pa[2] = packh(sc[2 * t + 1][0], sc[2 * t + 1][1]);
            pa[3] = packh(sc[2 * t + 1][2], sc[2 * t + 1][3]);
            uint32_t vbase = smem_u32(Vs + (t * 16 + lrow) * AST + lsel * 8);
            #pragma unroll
            for (int ni2 = 0; ni2 < 8; ni2++) {
                uint32_t r0, r1, r2, r3;
                asm volatile(
                    "ldmatrix.sync.aligned.m8n8.x4.trans.shared.b16 {%0,%1,%2,%3}, [%4];"
                    : "=r"(r0), "=r"(r1), "=r"(r2), "=r"(r3)
                    : "r"(vbase + ni2 * 32u));
                mma_f16(of[2 * ni2], pa, r0, r1);
                mma_f16(of[2 * ni2 + 1], pa, r2, r3);
            }
        }
        __syncthreads();
    }

    // epilogue: normalize, write fp16 (b,s,h,d)
    float inv0 = 1.f / l0, inv1 = 1.f / l1;
    long r0 = bS + (long)qb * 128 + wq + gid;
    long r1 = r0 + 8;
    #pragma unroll
    for (int nt = 0; nt < 16; nt++) {
        int d = nt * 8 + tig * 2;
        *(uint32_t*)(o + (r0 * NH_ + h) * DH_ + d) = packh(of[nt][0] * inv0, of[nt][1] * inv0);
        *(uint32_t*)(o + (r1 * NH_ + h) * DH_ + d) = packh(of[nt][2] * inv1, of[nt][3] * inv1);
    }
}

// ---------------- launch ----------------
extern "C" void kernel_launch(void* const* d_in, const int* in_sizes, int n_in,
                              void* d_out, int out_size) {
    const float* hidden = (const float*)d_in[0];
    const float* cosp   = (const float*)d_in[1];
    const float* sinp   = (const float*)d_in[2];
    const float* wq     = (const float*)d_in[3];
    const float* wk     = (const float*)d_in[4];
    const float* wv     = (const float*)d_in[5];
    const float* wo     = (const float*)d_in[6];
    const float* qnw    = (const float*)d_in[7];
    const float* knw    = (const float*)d_in[8];
    const float* anw    = (const float*)d_in[9];
    const float* mnw    = (const float*)d_in[10];
    const float* wgate  = (const float*)d_in[11];
    const float* wup    = (const float*)d_in[12];
    const float* wdown  = (const float*)d_in[13];
    float* out = (float*)d_out;

    __half *xnorm, *q16, *k16, *v16, *attn, *x2, *act, *Wqkv, *Wo, *Wgu, *Wdn;
    float *qkv, *h1;
    cudaGetSymbolAddress((void**)&xnorm, g_xnorm16);
    cudaGetSymbolAddress((void**)&qkv, g_qkv);
    cudaGetSymbolAddress((void**)&q16, g_q16);
    cudaGetSymbolAddress((void**)&k16, g_k16);
    cudaGetSymbolAddress((void**)&v16, g_v16);
    cudaGetSymbolAddress((void**)&attn, g_attn16);
    cudaGetSymbolAddress((void**)&h1, g_h1);
    cudaGetSymbolAddress((void**)&x2, g_x216);
    cudaGetSymbolAddress((void**)&act, g_act16);
    cudaGetSymbolAddress((void**)&Wqkv, w_qkv);
    cudaGetSymbolAddress((void**)&Wo, w_o);
    cudaGetSymbolAddress((void**)&Wgu, w_gu);
    cudaGetSymbolAddress((void**)&Wdn, w_dn);

    cudaFuncSetAttribute(attn_kernel, cudaFuncAttributeMaxDynamicSharedMemorySize, AT_SMEM_BYTES);
    cudaFuncSetAttribute(gemm_f16, cudaFuncAttributeMaxDynamicSharedMemorySize, GEMM_SMEM_BYTES);

    // 0) transpose + fp16-convert weights -> Wt[n][k]; gate/up interleaved
    dim3 tb(256);
    transpose_cvt_h<<<dim3(H_ / 64, H_ / 64), tb>>>(wq, Wqkv, H_, H_, 0, 1);
    transpose_cvt_h<<<dim3(512 / 64, H_ / 64), tb>>>(wk, Wqkv, H_, 512, 2048, 1);
    transpose_cvt_h<<<dim3(512 / 64, H_ / 64), tb>>>(wv, Wqkv, H_, 512, 2560, 1);
    transpose_cvt_h<<<dim3(H_ / 64, H_ / 64), tb>>>(wo, Wo, H_, H_, 0, 1);
    transpose_cvt_h<<<dim3(I_ / 64, H_ / 64), tb>>>(wgate, Wgu, H_, I_, 0, 2);
    transpose_cvt_h<<<dim3(I_ / 64, H_ / 64), tb>>>(wup, Wgu, H_, I_, 1, 2);
    transpose_cvt_h<<<dim3(H_ / 64, I_ / 64), tb>>>(wdown, Wdn, I_, H_, 0, 1);

    // 1) attn rmsnorm (fp16 out)
    rmsnorm_kernel<<<M_, 256>>>(hidden, anw, xnorm, H_);

    // 2) fused QKV projection (fp32 out)
    gemm_f16<<<dim3(QKV_N_ / 256, M_ / 128), 256, GEMM_SMEM_BYTES>>>(
        xnorm, Wqkv, nullptr, qkv, nullptr, QKV_N_, H_, 0);

    // 3) q/k norm + rope -> fp16 head-major; v convert
    const float qscale = 0.08838834764831845f;   // 1/sqrt(128)
    qknorm_rope_kernel<<<M_ * NH_, DH_>>>(qkv, 0, qnw, cosp, sinp, NH_, q16, qscale);
    qknorm_rope_kernel<<<M_ * NKV_, DH_>>>(qkv, 2048, knw, cosp, sinp, NKV_, k16, 1.0f);
    {
        long total4 = (long)M_ * 512 / 4;
        vcvt_kernel<<<(int)((total4 + 255) / 256), 256>>>(qkv, v16);
    }

    // 4) attention (fp16 mma, cp.async double-buffer)
    attn_kernel<<<dim3(S_ / 128, NH_, B_), 256, AT_SMEM_BYTES>>>(q16, k16, v16, attn);

    // 5) O projection + residual (fp32 out)
    gemm_f16<<<dim3(H_ / 256, M_ / 128), 256, GEMM_SMEM_BYTES>>>(
        attn, Wo, hidden, h1, nullptr, H_, H_, 0);

    // 6) mlp rmsnorm (fp16 out)
    rmsnorm_kernel<<<M_, 256>>>(h1, mnw, x2, H_);

    // 7) fused gate+up projection, silu fused in epilogue (fp16 act out)
    gemm_f16<<<dim3(GU_N_ / 256, M_ / 128), 256, GEMM_SMEM_BYTES>>>(
        x2, Wgu, nullptr, nullptr, act, GU_N_, H_, 1);

    // 8) down projection + residual -> output (fp32)
    gemm_f16<<<dim3(H_ / 256, M_ / 128), 256, GEMM_SMEM_BYTES>>>(
        act, Wdn, h1, out, nullptr, H_, I_, 0);
}